// round 7
// baseline (speedup 1.0000x reference)
#include <cuda_runtime.h>
#include <cstdint>

#define CH   256
#define IMG  128
#define HW   (IMG*IMG)
#define BATCH 4
#define HEADS 4
#define D    64
#define BLK  8
#define HALO 3
#define WIN  14
#define NB   16
#define NPOS 64
#define NWIN 196

typedef unsigned long long ull;

__device__ __forceinline__ ull pack2(float lo, float hi) {
    ull r; asm("mov.b64 %0, {%1,%2};" : "=l"(r) : "f"(lo), "f"(hi)); return r;
}
__device__ __forceinline__ ull pack2b(float v) { return pack2(v, v); }
__device__ __forceinline__ void fma2(ull& d, ull a, ull b) {
    asm("fma.rn.f32x2 %0, %1, %2, %0;" : "+l"(d) : "l"(a), "l"(b));
}
__device__ __forceinline__ void unpack2(ull v, float& lo, float& hi) {
    asm("mov.b64 {%0,%1}, %2;" : "=f"(lo), "=f"(hi) : "l"(v));
}
__device__ __forceinline__ float tf32r(float x) {
    uint32_t r; asm("cvt.rna.tf32.f32 %0, %1;" : "=r"(r) : "f"(x));
    return __uint_as_float(r);
}
__device__ __forceinline__ void mma8(float* d, uint32_t a0, uint32_t a1,
                                     uint32_t a2, uint32_t a3,
                                     uint32_t b0, uint32_t b1) {
    asm("mma.sync.aligned.m16n8k8.row.col.f32.tf32.tf32.f32 "
        "{%0,%1,%2,%3},{%4,%5,%6,%7},{%8,%9},{%0,%1,%2,%3};"
        : "+f"(d[0]), "+f"(d[1]), "+f"(d[2]), "+f"(d[3])
        : "r"(a0), "r"(a1), "r"(a2), "r"(a3), "r"(b0), "r"(b1));
}

// Scratch; g_k/g_v padded 16 floats front+back for aligned halo float4 loads.
__device__ float g_naux[(long)BATCH*CH*HW];
__device__ float g_q   [(long)BATCH*CH*HW];
__device__ float g_k   [(long)BATCH*CH*HW + 32];
__device__ float g_v   [(long)BATCH*CH*HW + 32];

// ---------------------------------------------------------------------------
// Conv1x1 GEMM (f32x2, at packed-fp32 roofline) — unchanged.
// ---------------------------------------------------------------------------
__global__ __launch_bounds__(256, 2)
void gemm_conv(const float* __restrict__ A,
               const float* __restrict__ B0,
               const float* __restrict__ B1,
               int K, int K0,
               float* __restrict__ C,
               const float* __restrict__ bias,
               float scale, int mode)
{
    const int tid = threadIdx.x;
    const int b   = blockIdx.z;
    const int n0  = blockIdx.x * 128;
    const int m0  = blockIdx.y * 128;
    const long boff = (long)b * CH * HW;
    const float* Bb0 = B0 + boff;
    const float* Bb1 = B1 ? (B1 + boff) : nullptr;
    float* Cb = C + boff;

    __shared__ float As[2][16][132];
    __shared__ float Bs[2][16][128];

    const int ty8 = (tid >> 4) * 8;
    const int tx8 = (tid & 15) * 8;
    const int arow0 = tid >> 2;
    const int acol  = (tid & 3) * 4;
    const int brow0 = tid >> 5;
    const int bcol  = (tid & 31) * 4;

    ull acc[8][4];
#pragma unroll
    for (int i = 0; i < 8; i++)
#pragma unroll
        for (int q = 0; q < 4; q++) acc[i][q] = 0ull;

    const int ntiles = K / 16;
    float4 ar[2], br[2];

#pragma unroll
    for (int p = 0; p < 2; p++)
        ar[p] = *(const float4*)&A[(long)(m0 + p * 64 + arow0) * K + acol];
#pragma unroll
    for (int p = 0; p < 2; p++) {
        int kr = p * 8 + brow0;
        const float* src = (kr < K0) ? (Bb0 + (long)kr * HW)
                                     : (Bb1 + (long)(kr - K0) * HW);
        br[p] = *(const float4*)&src[n0 + bcol];
    }
#pragma unroll
    for (int p = 0; p < 2; p++) {
        int row = p * 64 + arow0;
        As[0][acol + 0][row] = ar[p].x;
        As[0][acol + 1][row] = ar[p].y;
        As[0][acol + 2][row] = ar[p].z;
        As[0][acol + 3][row] = ar[p].w;
    }
#pragma unroll
    for (int p = 0; p < 2; p++)
        *(float4*)&Bs[0][p * 8 + brow0][bcol] = br[p];
    __syncthreads();

    for (int kt = 0; kt < ntiles; kt++) {
        const int cur = kt & 1, nxt = cur ^ 1;
        if (kt + 1 < ntiles) {
            int kb = (kt + 1) * 16;
#pragma unroll
            for (int p = 0; p < 2; p++)
                ar[p] = *(const float4*)&A[(long)(m0 + p * 64 + arow0) * K + kb + acol];
#pragma unroll
            for (int p = 0; p < 2; p++) {
                int kr = kb + p * 8 + brow0;
                const float* src = (kr < K0) ? (Bb0 + (long)kr * HW)
                                             : (Bb1 + (long)(kr - K0) * HW);
                br[p] = *(const float4*)&src[n0 + bcol];
            }
        }
#pragma unroll
        for (int kk = 0; kk < 16; kk++) {
            float4 a0 = *(const float4*)&As[cur][kk][ty8];
            float4 a1 = *(const float4*)&As[cur][kk][ty8 + 4];
            float4 b0 = *(const float4*)&Bs[cur][kk][tx8];
            float4 b1 = *(const float4*)&Bs[cur][kk][tx8 + 4];
            float a[8] = {a0.x,a0.y,a0.z,a0.w,a1.x,a1.y,a1.z,a1.w};
            ull b2[4] = {pack2(b0.x,b0.y), pack2(b0.z,b0.w),
                         pack2(b1.x,b1.y), pack2(b1.z,b1.w)};
#pragma unroll
            for (int i = 0; i < 8; i++) {
                ull ai = pack2b(a[i]);
#pragma unroll
                for (int q = 0; q < 4; q++) fma2(acc[i][q], ai, b2[q]);
            }
        }
        if (kt + 1 < ntiles) {
#pragma unroll
            for (int p = 0; p < 2; p++) {
                int row = p * 64 + arow0;
                As[nxt][acol + 0][row] = ar[p].x;
                As[nxt][acol + 1][row] = ar[p].y;
                As[nxt][acol + 2][row] = ar[p].z;
                As[nxt][acol + 3][row] = ar[p].w;
            }
#pragma unroll
            for (int p = 0; p < 2; p++)
                *(float4*)&Bs[nxt][p * 8 + brow0][bcol] = br[p];
            __syncthreads();
        }
    }

#pragma unroll
    for (int i = 0; i < 8; i++) {
        int o = m0 + ty8 + i;
        float bi = (mode == 0) ? bias[o] : 0.f;
        float c[8];
#pragma unroll
        for (int q = 0; q < 4; q++) unpack2(acc[i][q], c[2*q], c[2*q+1]);
#pragma unroll
        for (int j = 0; j < 8; j++) {
            if (mode == 0)      c[j] = fmaxf(c[j] + bi, 0.f);
            else if (mode == 1) c[j] = c[j] * scale;
        }
        float* dst = &Cb[(long)o * HW + n0 + tx8];
        *(float4*)&dst[0] = make_float4(c[0], c[1], c[2], c[3]);
        *(float4*)&dst[4] = make_float4(c[4], c[5], c[6], c[7]);
    }
}

// ---------------------------------------------------------------------------
// Halo attention v6: 512 threads / CTA, 1 CTA/SM, all loads up front,
// tf32 mma for QK^T and AV, staged coalesced output.
// smem (floats):
//   KW  @0      [208][68]  (rows 196..207 zero)  -> simT / OT overlay
//   QC  @14144  [64][72]
//   VC  @18752  [64][204]  (cols 196..203 zero)
//   REL @31808 (896), RED @32704 (8x64), MX @33216, INV @33280; TOT 33344
// ---------------------------------------------------------------------------
#define KW_OFF   0
#define KW_STR   68
#define QC_OFF   14144
#define QC_STR   72
#define VC_OFF   18752
#define VC_STR   204
#define ST_OFF   0
#define ST_STR   68
#define OT_OFF   0
#define OT_STR   72
#define REL_OFF  31808
#define RED_OFF  32704
#define MX_OFF   33216
#define INV_OFF  33280
#define SM_TOT   33344

__global__ __launch_bounds__(512, 1)
void attn_kernel(const float* __restrict__ gq, const float* __restrict__ gk,
                 const float* __restrict__ gv, const float* __restrict__ relh,
                 const float* __restrict__ relw, float* __restrict__ out)
{
    extern __shared__ float sm[];
    const int tid  = threadIdx.x;
    const int lane = tid & 31, w = tid >> 5;
    const int gid  = lane >> 2, tig = lane & 3;
    const int blk = blockIdx.x;
    const int h   = blockIdx.y;
    const int b   = blockIdx.z;
    const int by  = blk >> 4, bx = blk & 15;
    const int y0  = by * BLK, x0 = bx * BLK;
    const long base = ((long)b * CH + h * D) * HW;

    // ---- phase 0: rel tables + zero pads ------------------------------------
    for (int t = tid; t < 896; t += 512) {
        if (t < 448) sm[REL_OFF + t] = relh[t];
        else {
            int m = t - 448, jw = m >> 5, cc = m & 31;
            sm[REL_OFF + 448 + cc * 14 + jw] = relw[m];
        }
    }
    for (int t = tid; t < 12 * KW_STR; t += 512)
        sm[KW_OFF + 196 * KW_STR + t] = 0.f;
    {   // VC cols 196..203 zero
        int c = tid >> 3, q2 = tid & 7;
        sm[VC_OFF + c * VC_STR + 196 + q2] = 0.f;
    }
    __syncthreads();

    // ---- phase 1: load Q, K(+bias), V — all LDGs in flight together ---------
    {   // Q: one (c,row) per thread
        int c = tid >> 3, r = tid & 7;
        const float* src = gq + base + (long)c * HW + (y0 + r) * IMG + x0;
        float4 qa = *(const float4*)src;
        float4 qb = *(const float4*)(src + 4);
        qa.x=tf32r(qa.x); qa.y=tf32r(qa.y); qa.z=tf32r(qa.z); qa.w=tf32r(qa.w);
        qb.x=tf32r(qb.x); qb.y=tf32r(qb.y); qb.z=tf32r(qb.z); qb.w=tf32r(qb.w);
        *(float4*)&sm[QC_OFF + c * QC_STR + r * 8]     = qa;
        *(float4*)&sm[QC_OFF + c * QC_STR + r * 8 + 4] = qb;
    }
    for (int t = tid; t < 896; t += 512) {     // K window rows
        int c = t / 14, iw = t - c * 14;
        int y = y0 - HALO + iw;
        float wv[16];
        if ((unsigned)y < IMG) {
            const float* src = gk + base + (long)c * HW + y * IMG + x0 - 4;
            float4 f0 = *(const float4*)src;
            float4 f1 = *(const float4*)(src + 4);
            float4 f2 = *(const float4*)(src + 8);
            float4 f3 = *(const float4*)(src + 12);
            wv[0]=f0.x; wv[1]=f0.y; wv[2]=f0.z; wv[3]=f0.w;
            wv[4]=f1.x; wv[5]=f1.y; wv[6]=f1.z; wv[7]=f1.w;
            wv[8]=f2.x; wv[9]=f2.y; wv[10]=f2.z; wv[11]=f2.w;
            wv[12]=f3.x; wv[13]=f3.y; wv[14]=f3.z; wv[15]=f3.w;
            if (x0 == 0)   { wv[1]=0.f; wv[2]=0.f; wv[3]=0.f; }
            if (x0 == 120) { wv[12]=0.f; wv[13]=0.f; wv[14]=0.f; }
        } else {
#pragma unroll
            for (int m = 0; m < 16; m++) wv[m] = 0.f;
        }
        if (c < 32) {
            float bh = sm[REL_OFF + iw * 32 + c];
#pragma unroll
            for (int jw = 0; jw < 14; jw++)
                sm[KW_OFF + (iw * 14 + jw) * KW_STR + c] = tf32r(wv[jw + 1] + bh);
        } else {
            const float* rw = &sm[REL_OFF + 448 + (c - 32) * 14];
#pragma unroll
            for (int jw = 0; jw < 14; jw++)
                sm[KW_OFF + (iw * 14 + jw) * KW_STR + c] = tf32r(wv[jw + 1] + rw[jw]);
        }
    }
    for (int t = tid; t < 896; t += 512) {     // V window rows
        int c = t / 14, iw = t - c * 14;
        int y = y0 - HALO + iw;
        float wv[16];
        if ((unsigned)y < IMG) {
            const float* src = gv + base + (long)c * HW + y * IMG + x0 - 4;
            float4 f0 = *(const float4*)src;
            float4 f1 = *(const float4*)(src + 4);
            float4 f2 = *(const float4*)(src + 8);
            float4 f3 = *(const float4*)(src + 12);
            wv[0]=f0.x; wv[1]=f0.y; wv[2]=f0.z; wv[3]=f0.w;
            wv[4]=f1.x; wv[5]=f1.y; wv[6]=f1.z; wv[7]=f1.w;
            wv[8]=f2.x; wv[9]=f2.y; wv[10]=f2.z; wv[11]=f2.w;
            wv[12]=f3.x; wv[13]=f3.y; wv[14]=f3.z; wv[15]=f3.w;
            if (x0 == 0)   { wv[1]=0.f; wv[2]=0.f; wv[3]=0.f; }
            if (x0 == 120) { wv[12]=0.f; wv[13]=0.f; wv[14]=0.f; }
        } else {
#pragma unroll
            for (int m = 0; m < 16; m++) wv[m] = 0.f;
        }
        float* dst = &sm[VC_OFF + c * VC_STR + iw * 14];
#pragma unroll
        for (int jw = 0; jw < 14; jw++) dst[jw] = tf32r(wv[jw + 1]);
    }
    __syncthreads();

    // ---- phase 2: simT[208 x 64] = KW @ QC (16 warps: 13 m-tiles x 4 n-grp) --
    const int wm = w >> 2, wn = w & 3;
    const int mcnt  = (wm == 0) ? 4 : 3;
    const int mbase = ((wm == 0) ? 0 : (1 + 3 * wm)) * 16;
    float Cf[4][2][4];
#pragma unroll
    for (int mt = 0; mt < 4; mt++)
#pragma unroll
        for (int nt = 0; nt < 2; nt++)
#pragma unroll
            for (int q = 0; q < 4; q++) Cf[mt][nt][q] = 0.f;

#pragma unroll
    for (int ks = 0; ks < 8; ks++) {
        const int c0 = ks * 8;
        uint32_t Bf[2][2];
#pragma unroll
        for (int nt = 0; nt < 2; nt++) {
            int n = wn * 16 + nt * 8 + gid;
            Bf[nt][0] = __float_as_uint(sm[QC_OFF + (c0 + tig)     * QC_STR + n]);
            Bf[nt][1] = __float_as_uint(sm[QC_OFF + (c0 + tig + 4) * QC_STR + n]);
        }
#pragma unroll
        for (int mt = 0; mt < 4; mt++) {
            if (mt < mcnt) {
                int r = mbase + mt * 16 + gid;
                uint32_t a0 = __float_as_uint(sm[KW_OFF + r       * KW_STR + c0 + tig]);
                uint32_t a1 = __float_as_uint(sm[KW_OFF + (r + 8) * KW_STR + c0 + tig]);
                uint32_t a2 = __float_as_uint(sm[KW_OFF + r       * KW_STR + c0 + tig + 4]);
                uint32_t a3 = __float_as_uint(sm[KW_OFF + (r + 8) * KW_STR + c0 + tig + 4]);
                mma8(Cf[mt][0], a0, a1, a2, a3, Bf[0][0], Bf[0][1]);
                mma8(Cf[mt][1], a0, a1, a2, a3, Bf[1][0], Bf[1][1]);
            }
        }
    }
    __syncthreads();   // KW dead

#pragma unroll
    for (int mt = 0; mt < 4; mt++) {
        if (mt < mcnt) {
#pragma unroll
            for (int nt = 0; nt < 2; nt++) {
                int r = mbase + mt * 16 + gid;
                int cidx = wn * 16 + nt * 8 + 2 * tig;
                *(float2*)&sm[ST_OFF + r * ST_STR + cidx] =
                    make_float2(Cf[mt][nt][0], Cf[mt][nt][1]);
                *(float2*)&sm[ST_OFF + (r + 8) * ST_STR + cidx] =
                    make_float2(Cf[mt][nt][2], Cf[mt][nt][3]);
            }
        }
    }
    __syncthreads();

    // ---- phase 4: softmax over j per column i (8 j-groups) ------------------
    {
        const int i = tid & 63, p = tid >> 6;
        const int cnt = (p < 4) ? 25 : 24;
        const int jb  = (p < 4) ? p * 25 : 100 + (p - 4) * 24;
        float m = -1e30f;
        for (int jj = 0; jj < cnt; jj++)
            m = fmaxf(m, sm[ST_OFF + (jb + jj) * ST_STR + i]);
        sm[RED_OFF + p * 64 + i] = m;
        __syncthreads();
        if (tid < 64) {
            float mm = -1e30f;
#pragma unroll
            for (int pp = 0; pp < 8; pp++)
                mm = fmaxf(mm, sm[RED_OFF + pp * 64 + tid]);
            sm[MX_OFF + tid] = mm;
        }
        __syncthreads();
        float mm = sm[MX_OFF + i];
        float s = 0.f;
        for (int jj = 0; jj < cnt; jj++) {
            float e = __expf(sm[ST_OFF + (jb + jj) * ST_STR + i] - mm);
            s += e;
            sm[ST_OFF + (jb + jj) * ST_STR + i] = tf32r(e);
        }
        sm[RED_OFF + p * 64 + i] = s;
        if (tid < 4 * ST_STR) sm[ST_OFF + 196 * ST_STR + tid] = 0.f;  // AV k-pad
        __syncthreads();
        if (tid < 64) {
            float ss = 0.f;
#pragma unroll
            for (int pp = 0; pp < 8; pp++)
                ss += sm[RED_OFF + pp * 64 + tid];
            sm[INV_OFF + tid] = 1.f / ss;
        }
        __syncthreads();
    }

    // ---- phase 5: outT[64c x 64i] = VC @ simT (16 warps: 4x4 grid) ----------
    {
        const int c0 = (w >> 2) * 16;
        const int i0 = (w & 3) * 16;
        float Df[2][4];
#pragma unroll
        for (int nt = 0; nt < 2; nt++)
#pragma unroll
            for (int q = 0; q < 4; q++) Df[nt][q] = 0.f;

        for (int kt = 0; kt < 25; kt++) {
            const int j0 = kt * 8;
            const int cr = c0 + gid;
            uint32_t a0 = __float_as_uint(sm[VC_OFF + cr       * VC_STR + j0 + tig]);
            uint32_t a1 = __float_as_uint(sm[VC_OFF + (cr + 8) * VC_STR + j0 + tig]);
            uint32_t a2 = __float_as_uint(sm[VC_OFF + cr       * VC_STR + j0 + tig + 4]);
            uint32_t a3 = __float_as_uint(sm[VC_OFF + (cr + 8) * VC_STR + j0 + tig + 4]);
#pragma unroll
            for (int nt = 0; nt < 2; nt++) {
                int n = i0 + nt * 8 + gid;
                uint32_t b0 = __float_as_uint(sm[ST_OFF + (j0 + tig)     * ST_STR + n]);
                uint32_t b1 = __float_as_uint(sm[ST_OFF + (j0 + tig + 4) * ST_STR + n]);
                mma8(Df[nt], a0, a1, a2, a3, b0, b1);
            }
        }
        __syncthreads();   // simT dead; overlay OT

#pragma unroll
        for (int nt = 0; nt < 2; nt++) {
            int ii = i0 + nt * 8 + 2 * tig;
            float v0 = sm[INV_OFF + ii], v1 = sm[INV_OFF + ii + 1];
            int cr = c0 + gid;
            *(float2*)&sm[OT_OFF + cr * OT_STR + ii] =
                make_float2(Df[nt][0] * v0, Df[nt][1] * v1);
            *(float2*)&sm[OT_OFF + (cr + 8) * OT_STR + ii] =
                make_float2(Df[nt][2] * v0, Df[nt][3] * v1);
        }
        __syncthreads();

        // coalesced output: one (c,row) per thread, 2x STG.128
        int c = tid >> 3, r = tid & 7;
        float4 o0 = *(const float4*)&sm[OT_OFF + c * OT_STR + r * 8];
        float4 o1 = *(const float4*)&sm[OT_OFF + c * OT_STR + r * 8 + 4];
        float* dst = out + base + (long)c * HW + (y0 + r) * IMG + x0;
        *(float4*)&dst[0] = o0;
        *(float4*)&dst[4] = o1;
    }
}

// ---------------------------------------------------------------------------
extern "C" void kernel_launch(void* const* d_in, const int* in_sizes, int n_in,
                              void* d_out, int out_size)
{
    const float* noisy = (const float*)d_in[0];
    const float* aux   = (const float*)d_in[1];
    const float* w_map = (const float*)d_in[2];
    const float* b_map = (const float*)d_in[3];
    const float* w_q   = (const float*)d_in[4];
    const float* w_k   = (const float*)d_in[5];
    const float* w_v   = (const float*)d_in[6];
    const float* rel_h = (const float*)d_in[7];
    const float* rel_w = (const float*)d_in[8];
    float* out = (float*)d_out;

    float *naux, *q, *kraw, *vraw;
    cudaGetSymbolAddress((void**)&naux, g_naux);
    cudaGetSymbolAddress((void**)&q,    g_q);
    cudaGetSymbolAddress((void**)&kraw, g_k);
    cudaGetSymbolAddress((void**)&vraw, g_v);
    float* k = kraw + 16;
    float* v = vraw + 16;

    dim3 ggrid(HW / 128, CH / 128, BATCH);

    gemm_conv<<<ggrid, 256>>>(w_map, noisy, aux, 2 * CH, CH, naux, b_map, 1.f, 0);
    gemm_conv<<<ggrid, 256>>>(w_q, naux, nullptr, CH, CH, q, nullptr, 0.125f, 1);
    gemm_conv<<<ggrid, 256>>>(w_k, naux, nullptr, CH, CH, k, nullptr, 1.f, 2);
    gemm_conv<<<ggrid, 256>>>(w_v, noisy, nullptr, CH, CH, v, nullptr, 1.f, 2);

    size_t smem = (size_t)SM_TOT * sizeof(float);   // 133,376 B
    cudaFuncSetAttribute(attn_kernel,
                         cudaFuncAttributeMaxDynamicSharedMemorySize, (int)smem);
    attn_kernel<<<dim3(NB * NB, HEADS, BATCH), 512, smem>>>(q, k, v, rel_h, rel_w, out);
}

// round 8
// speedup vs baseline: 1.0422x; 1.0422x over previous
#include <cuda_runtime.h>
#include <cstdint>

#define CH   256
#define IMG  128
#define HW   (IMG*IMG)
#define BATCH 4
#define HEADS 4
#define NB   16
#define BLK  8
#define HALO 3

typedef unsigned long long ull;

__device__ __forceinline__ ull pack2(float lo, float hi) {
    ull r; asm("mov.b64 %0, {%1,%2};" : "=l"(r) : "f"(lo), "f"(hi)); return r;
}
__device__ __forceinline__ ull pack2b(float v) { return pack2(v, v); }
__device__ __forceinline__ void fma2(ull& d, ull a, ull b) {
    asm("fma.rn.f32x2 %0, %1, %2, %0;" : "+l"(d) : "l"(a), "l"(b));
}
__device__ __forceinline__ void unpack2(ull v, float& lo, float& hi) {
    asm("mov.b64 {%0,%1}, %2;" : "=f"(lo), "=f"(hi) : "l"(v));
}
__device__ __forceinline__ float tf32r(float x) {
    uint32_t r; asm("cvt.rna.tf32.f32 %0, %1;" : "=r"(r) : "f"(x));
    return __uint_as_float(r);
}
__device__ __forceinline__ void mma8(float* d, uint32_t a0, uint32_t a1,
                                     uint32_t a2, uint32_t a3,
                                     uint32_t b0, uint32_t b1) {
    asm("mma.sync.aligned.m16n8k8.row.col.f32.tf32.tf32.f32 "
        "{%0,%1,%2,%3},{%4,%5,%6,%7},{%8,%9},{%0,%1,%2,%3};"
        : "+f"(d[0]), "+f"(d[1]), "+f"(d[2]), "+f"(d[3])
        : "r"(a0), "r"(a1), "r"(a2), "r"(a3), "r"(b0), "r"(b1));
}

// Pixel-major scratch [b][p][256] + transposed weights.
__device__ float g_naux[(long)BATCH*HW*CH];
__device__ float g_q   [(long)BATCH*HW*CH];
__device__ float g_k   [(long)BATCH*HW*CH];
__device__ float g_v   [(long)BATCH*HW*CH];
__device__ float g_wt  [512*256 + 3*256*256];

__global__ void transpose_w(const float* __restrict__ wm,
                            const float* __restrict__ wq,
                            const float* __restrict__ wk,
                            const float* __restrict__ wv,
                            float* __restrict__ wt)
{
    int t = blockIdx.x * 256 + threadIdx.x;
    if (t < 131072)      { int k = t >> 8, o = t & 255; wt[t] = wm[o * 512 + k]; }
    else if (t < 196608) { int u = t - 131072; wt[t] = wq[(u & 255) * 256 + (u >> 8)]; }
    else if (t < 262144) { int u = t - 196608; wt[t] = wk[(u & 255) * 256 + (u >> 8)]; }
    else if (t < 327680) { int u = t - 262144; wt[t] = wv[(u & 255) * 256 + (u >> 8)]; }
}

// ---------------------------------------------------------------------------
// Conv1x1 GEMM -> pixel-major C[p][n]. AMODE 0: X c-major (concat Xa,Xb).
// AMODE 1: X pixel-major. B = Wt[k][n]. f32x2 inner loop.
// ---------------------------------------------------------------------------
template<int AMODE>
__global__ __launch_bounds__(256, 2)
void gemm_conv(const float* __restrict__ Xa, const float* __restrict__ Xb,
               const float* __restrict__ Wt, int K, int KX0,
               float* __restrict__ C, const float* __restrict__ bias,
               float scale, int mode)
{
    const int tid = threadIdx.x;
    const int b   = blockIdx.z;
    const int m0  = blockIdx.x * 128;   // pixels
    const int n0  = blockIdx.y * 128;   // out channels
    const long boff = (long)b * CH * HW;
    const float* Xab = Xa + boff;
    const float* Xbb = Xb ? (Xb + boff) : nullptr;
    float* Cb = C + boff;

    __shared__ float As[2][16][132];
    __shared__ float Bs[2][16][128];

    const int ty8 = (tid >> 4) * 8;
    const int tx8 = (tid & 15) * 8;
    const int arow0 = tid >> 2, acol = (tid & 3) * 4;    // AMODE 1
    const int akk = tid >> 4,  amq  = (tid & 15) * 8;    // AMODE 0
    const int brow0 = tid >> 5, bcol = (tid & 31) * 4;

    ull acc[8][4];
#pragma unroll
    for (int i = 0; i < 8; i++)
#pragma unroll
        for (int q = 0; q < 4; q++) acc[i][q] = 0ull;

    const int ntiles = K / 16;
    float4 ar[2], br[2];

    auto loadA = [&](int kb) {
        if (AMODE == 0) {
            int kr = kb + akk;
            const float* s = (kr < KX0) ? (Xab + (long)kr * HW)
                                        : (Xbb + (long)(kr - KX0) * HW);
            ar[0] = *(const float4*)&s[m0 + amq];
            ar[1] = *(const float4*)&s[m0 + amq + 4];
        } else {
#pragma unroll
            for (int p = 0; p < 2; p++)
                ar[p] = *(const float4*)&Xab[(long)(m0 + p * 64 + arow0) * K + kb + acol];
        }
    };
    auto loadB = [&](int kb) {
#pragma unroll
        for (int p = 0; p < 2; p++)
            br[p] = *(const float4*)&Wt[(long)(kb + p * 8 + brow0) * 256 + n0 + bcol];
    };
    auto storeA = [&](int buf) {
        if (AMODE == 0) {
            *(float4*)&As[buf][akk][amq]     = ar[0];
            *(float4*)&As[buf][akk][amq + 4] = ar[1];
        } else {
#pragma unroll
            for (int p = 0; p < 2; p++) {
                int row = p * 64 + arow0;
                As[buf][acol + 0][row] = ar[p].x;
                As[buf][acol + 1][row] = ar[p].y;
                As[buf][acol + 2][row] = ar[p].z;
                As[buf][acol + 3][row] = ar[p].w;
            }
        }
    };
    auto storeB = [&](int buf) {
#pragma unroll
        for (int p = 0; p < 2; p++)
            *(float4*)&Bs[buf][p * 8 + brow0][bcol] = br[p];
    };

    loadA(0); loadB(0); storeA(0); storeB(0);
    __syncthreads();

    for (int kt = 0; kt < ntiles; kt++) {
        const int cur = kt & 1, nxt = cur ^ 1;
        if (kt + 1 < ntiles) { loadA((kt + 1) * 16); loadB((kt + 1) * 16); }
#pragma unroll
        for (int kk = 0; kk < 16; kk++) {
            float4 a0 = *(const float4*)&As[cur][kk][ty8];
            float4 a1 = *(const float4*)&As[cur][kk][ty8 + 4];
            float4 b0 = *(const float4*)&Bs[cur][kk][tx8];
            float4 b1 = *(const float4*)&Bs[cur][kk][tx8 + 4];
            float a[8] = {a0.x,a0.y,a0.z,a0.w,a1.x,a1.y,a1.z,a1.w};
            ull b2[4] = {pack2(b0.x,b0.y), pack2(b0.z,b0.w),
                         pack2(b1.x,b1.y), pack2(b1.z,b1.w)};
#pragma unroll
            for (int i = 0; i < 8; i++) {
                ull ai = pack2b(a[i]);
#pragma unroll
                for (int q = 0; q < 4; q++) fma2(acc[i][q], ai, b2[q]);
            }
        }
        if (kt + 1 < ntiles) { storeA(nxt); storeB(nxt); __syncthreads(); }
    }

    float bb[8];
    if (mode == 0) {
        float4 b0 = *(const float4*)&bias[n0 + tx8];
        float4 b1 = *(const float4*)&bias[n0 + tx8 + 4];
        bb[0]=b0.x; bb[1]=b0.y; bb[2]=b0.z; bb[3]=b0.w;
        bb[4]=b1.x; bb[5]=b1.y; bb[6]=b1.z; bb[7]=b1.w;
    }
#pragma unroll
    for (int i = 0; i < 8; i++) {
        float c[8];
#pragma unroll
        for (int q = 0; q < 4; q++) unpack2(acc[i][q], c[2*q], c[2*q+1]);
#pragma unroll
        for (int j = 0; j < 8; j++) {
            if (mode == 0)      c[j] = fmaxf(c[j] + bb[j], 0.f);
            else if (mode == 1) c[j] = c[j] * scale;
        }
        float* dst = &Cb[(long)(m0 + ty8 + i) * 256 + n0 + tx8];
        *(float4*)&dst[0] = make_float4(c[0], c[1], c[2], c[3]);
        *(float4*)&dst[4] = make_float4(c[4], c[5], c[6], c[7]);
    }
}

// ---------------------------------------------------------------------------
// Halo attention v7 (pixel-major). smem floats:
//   KW @0 [200][68] (rows 196-199 zero)   } overlay: simT[200][72], OT[64][68]
//   QI @13600 [64][68]                    }
//   VJ @17952 [200][72] (rows 196-199 zero)
//   RED @32352 [8][64], MX @32864, INV @32928; TOT 32992 (131,968 B)
// ---------------------------------------------------------------------------
#define KW_OFF 0
#define KW_STR 68
#define QI_OFF 13600
#define QI_STR 68
#define ST_OFF 0
#define ST_STR 72
#define VJ_OFF 17952
#define VJ_STR 72
#define OT_OFF 0
#define OT_STR 68
#define RED_OFF 32352
#define MX_OFF 32864
#define INV_OFF 32928
#define SM_TOT 32992

__global__ __launch_bounds__(512, 1)
void attn_kernel(const float* __restrict__ gq, const float* __restrict__ gk,
                 const float* __restrict__ gv, const float* __restrict__ relh,
                 const float* __restrict__ relw, float* __restrict__ out)
{
    extern __shared__ float sm[];
    const int tid  = threadIdx.x;
    const int lane = tid & 31, w = tid >> 5;
    const int gid  = lane >> 2, tig = lane & 3;
    const int by = blockIdx.x >> 4, bx = blockIdx.x & 15;
    const int h = blockIdx.y, b = blockIdx.z;
    const int y0 = by * BLK, x0 = bx * BLK;
    const long qbase = (long)b * HW * 256 + h * 64;
    const long obase = ((long)b * CH + h * 64) * HW;

    // ---- phase 1: zero pads, load Q/K(+bias)/V ------------------------------
    if (tid < 272)      sm[KW_OFF + 196 * KW_STR + tid] = 0.f;
    else if (tid < 560) sm[VJ_OFF + 196 * VJ_STR + (tid - 272)] = 0.f;

    if (tid < 256) {   // Q: 64 px x 4 quads of 16ch
        int px = tid >> 2, quad = tid & 3;
        int p = (y0 + (px >> 3)) * IMG + x0 + (px & 7);
        const float* src = gq + qbase + (long)p * 256 + quad * 16;
        float* dst = &sm[QI_OFF + px * QI_STR + quad * 16];
#pragma unroll
        for (int f = 0; f < 4; f++) {
            float4 v = *(const float4*)(src + f * 4);
            *(float4*)&dst[f * 4] = make_float4(tf32r(v.x), tf32r(v.y),
                                                tf32r(v.z), tf32r(v.w));
        }
    }
    for (int u = tid; u < 1568; u += 512) {   // K then V: 196 j x 4 quads each
        int isV = u >= 784;
        int e = isV ? u - 784 : u;
        int j = e >> 2, quad = e & 3;
        int iw = j / 14, jw = j - iw * 14;
        int yw = y0 - HALO + iw, xw = x0 - HALO + jw;
        bool valid = ((unsigned)yw < IMG) && ((unsigned)xw < IMG);
        int p = valid ? (yw * IMG + xw) : 0;
        if (!isV) {
            const float* src  = gk + qbase + (long)p * 256 + quad * 16;
            const float* bsrc = (quad < 2) ? (relh + iw * 32 + quad * 16)
                                           : (relw + jw * 32 + (quad - 2) * 16);
            float* dst = &sm[KW_OFF + j * KW_STR + quad * 16];
#pragma unroll
            for (int f = 0; f < 4; f++) {
                float4 bv = *(const float4*)(bsrc + f * 4);
                float4 kv = valid ? *(const float4*)(src + f * 4)
                                  : make_float4(0.f, 0.f, 0.f, 0.f);
                *(float4*)&dst[f * 4] =
                    make_float4(tf32r(kv.x + bv.x), tf32r(kv.y + bv.y),
                                tf32r(kv.z + bv.z), tf32r(kv.w + bv.w));
            }
        } else {
            const float* src = gv + qbase + (long)p * 256 + quad * 16;
            float* dst = &sm[VJ_OFF + j * VJ_STR + quad * 16];
#pragma unroll
            for (int f = 0; f < 4; f++) {
                float4 kv = valid ? *(const float4*)(src + f * 4)
                                  : make_float4(0.f, 0.f, 0.f, 0.f);
                *(float4*)&dst[f * 4] = make_float4(tf32r(kv.x), tf32r(kv.y),
                                                    tf32r(kv.z), tf32r(kv.w));
            }
        }
    }
    __syncthreads();

    // ---- phase 2: simT[j][i] = KW[j][c] x QI[i][c] (13 m-tiles x 4 n-grp) ---
    const int wm = w >> 2, wn = w & 3;
    const int mcnt   = (wm == 0) ? 4 : 3;
    const int mtile0 = (wm == 0) ? 0 : (4 + 3 * (wm - 1));
    float Cf[4][2][4];
#pragma unroll
    for (int mt = 0; mt < 4; mt++)
#pragma unroll
        for (int nt = 0; nt < 2; nt++)
#pragma unroll
            for (int q = 0; q < 4; q++) Cf[mt][nt][q] = 0.f;

#pragma unroll
    for (int ks = 0; ks < 8; ks++) {
        const int c0 = ks * 8;
        uint32_t Bf[2][2];
#pragma unroll
        for (int nt = 0; nt < 2; nt++) {
            int n = wn * 16 + nt * 8 + gid;
            Bf[nt][0] = __float_as_uint(sm[QI_OFF + n * QI_STR + c0 + tig]);
            Bf[nt][1] = __float_as_uint(sm[QI_OFF + n * QI_STR + c0 + tig + 4]);
        }
#pragma unroll
        for (int mt = 0; mt < 4; mt++) {
            if (mt < mcnt) {
                int r = (mtile0 + mt) * 16 + gid;
                uint32_t a0 = __float_as_uint(sm[KW_OFF + r       * KW_STR + c0 + tig]);
                uint32_t a1 = __float_as_uint(sm[KW_OFF + (r + 8) * KW_STR + c0 + tig]);
                uint32_t a2 = __float_as_uint(sm[KW_OFF + r       * KW_STR + c0 + tig + 4]);
                uint32_t a3 = __float_as_uint(sm[KW_OFF + (r + 8) * KW_STR + c0 + tig + 4]);
                mma8(Cf[mt][0], a0, a1, a2, a3, Bf[0][0], Bf[0][1]);
                mma8(Cf[mt][1], a0, a1, a2, a3, Bf[1][0], Bf[1][1]);
            }
        }
    }
    __syncthreads();   // KW/QI dead -> simT overlay

#pragma unroll
    for (int mt = 0; mt < 4; mt++) {
        if (mt < mcnt) {
#pragma unroll
            for (int nt = 0; nt < 2; nt++) {
                int r = (mtile0 + mt) * 16 + gid;
                int ci = wn * 16 + nt * 8 + 2 * tig;
                *(float2*)&sm[ST_OFF + r * ST_STR + ci] =
                    make_float2(Cf[mt][nt][0], Cf[mt][nt][1]);
                if (r + 8 < 200)
                    *(float2*)&sm[ST_OFF + (r + 8) * ST_STR + ci] =
                        make_float2(Cf[mt][nt][2], Cf[mt][nt][3]);
            }
        }
    }
    __syncthreads();

    // ---- phase 3: softmax over j per column i -------------------------------
    {
        const int i = tid & 63, p = tid >> 6;
        const int cnt = (p < 4) ? 25 : 24;
        const int jb  = (p < 4) ? p * 25 : 100 + (p - 4) * 24;
        float m = -1e30f;
        for (int jj = 0; jj < cnt; jj++)
            m = fmaxf(m, sm[ST_OFF + (jb + jj) * ST_STR + i]);
        sm[RED_OFF + p * 64 + i] = m;
        __syncthreads();
        if (tid < 64) {
            float mm = -1e30f;
#pragma unroll
            for (int pp = 0; pp < 8; pp++)
                mm = fmaxf(mm, sm[RED_OFF + pp * 64 + tid]);
            sm[MX_OFF + tid] = mm;
        }
        __syncthreads();
        float mm = sm[MX_OFF + i];
        float s = 0.f;
        for (int jj = 0; jj < cnt; jj++) {
            float e = __expf(sm[ST_OFF + (jb + jj) * ST_STR + i] - mm);
            s += e;
            sm[ST_OFF + (jb + jj) * ST_STR + i] = tf32r(e);
        }
        sm[RED_OFF + p * 64 + i] = s;
        if (tid < 4 * ST_STR) sm[ST_OFF + 196 * ST_STR + tid] = 0.f;
        __syncthreads();
        if (tid < 64) {
            float ss = 0.f;
#pragma unroll
            for (int pp = 0; pp < 8; pp++)
                ss += sm[RED_OFF + pp * 64 + tid];
            sm[INV_OFF + tid] = 1.f / ss;
        }
        __syncthreads();
    }

    // ---- phase 4: D[i][c] = attnT[i][j] x V[j][c]  (16 warps 4x4) -----------
    {
        const int ibase = (w >> 2) * 16;
        const int wn2 = w & 3;
        float Df[2][4];
#pragma unroll
        for (int nt = 0; nt < 2; nt++)
#pragma unroll
            for (int q = 0; q < 4; q++) Df[nt][q] = 0.f;

        for (int kt = 0; kt < 25; kt++) {
            const int j0 = kt * 8;
            uint32_t a0 = __float_as_uint(sm[ST_OFF + (j0 + tig)     * ST_STR + ibase + gid]);
            uint32_t a1 = __float_as_uint(sm[ST_OFF + (j0 + tig)     * ST_STR + ibase + gid + 8]);
            uint32_t a2 = __float_as_uint(sm[ST_OFF + (j0 + tig + 4) * ST_STR + ibase + gid]);
            uint32_t a3 = __float_as_uint(sm[ST_OFF + (j0 + tig + 4) * ST_STR + ibase + gid + 8]);
#pragma unroll
            for (int nt = 0; nt < 2; nt++) {
                int c0 = wn2 * 16 + nt * 8;
                uint32_t b0 = __float_as_uint(sm[VJ_OFF + (j0 + tig)     * VJ_STR + c0 + gid]);
                uint32_t b1 = __float_as_uint(sm[VJ_OFF + (j0 + tig + 4) * VJ_STR + c0 + gid]);
                mma8(Df[nt], a0, a1, a2, a3, b0, b1);
            }
        }
        float v0 = sm[INV_OFF + ibase + gid];
        float v1 = sm[INV_OFF + ibase + gid + 8];
        __syncthreads();   // simT/VJ dead -> OT overlay

#pragma unroll
        for (int nt = 0; nt < 2; nt++) {
            int c0 = wn2 * 16 + nt * 8;
            sm[OT_OFF + (c0 + 2*tig    ) * OT_STR + ibase + gid]     = Df[nt][0] * v0;
            sm[OT_OFF + (c0 + 2*tig + 1) * OT_STR + ibase + gid]     = Df[nt][1] * v0;
            sm[OT_OFF + (c0 + 2*tig    ) * OT_STR + ibase + gid + 8] = Df[nt][2] * v1;
            sm[OT_OFF + (c0 + 2*tig + 1) * OT_STR + ibase + gid + 8] = Df[nt][3] * v1;
        }
        __syncthreads();

        int c = tid >> 3, r = tid & 7;
        float4 o0 = *(const float4*)&sm[OT_OFF + c * OT_STR + r * 8];
        float4 o1 = *(const float4*)&sm[OT_OFF + c * OT_STR + r * 8 + 4];
        float* dst = out + obase + (long)c * HW + (y0 + r) * IMG + x0;
        *(float4*)&dst[0] = o0;
        *(float4*)&dst[4] = o1;
    }
}

// ---------------------------------------------------------------------------
extern "C" void kernel_launch(void* const* d_in, const int* in_sizes, int n_in,
                              void* d_out, int out_size)
{
    const float* noisy = (const float*)d_in[0];
    const float* aux   = (const float*)d_in[1];
    const float* w_map = (const float*)d_in[2];
    const float* b_map = (const float*)d_in[3];
    const float* w_q   = (const float*)d_in[4];
    const float* w_k   = (const float*)d_in[5];
    const float* w_v   = (const float*)d_in[6];
    const float* rel_h = (const float*)d_in[7];
    const float* rel_w = (const float*)d_in[8];
    float* out = (float*)d_out;

    float *naux, *q, *k, *v, *wt;
    cudaGetSymbolAddress((void**)&naux, g_naux);
    cudaGetSymbolAddress((void**)&q,    g_q);
    cudaGetSymbolAddress((void**)&k,    g_k);
    cudaGetSymbolAddress((void**)&v,    g_v);
    cudaGetSymbolAddress((void**)&wt,   g_wt);

    transpose_w<<<1280, 256>>>(w_map, w_q, w_k, w_v, wt);

    dim3 ggrid(HW / 128, CH / 128, BATCH);
    gemm_conv<0><<<ggrid, 256>>>(noisy, aux, wt,          512, 256, naux, b_map, 1.f,    0);
    gemm_conv<1><<<ggrid, 256>>>(naux, nullptr, wt+131072, 256, 0,   q,   nullptr, 0.125f, 1);
    gemm_conv<1><<<ggrid, 256>>>(naux, nullptr, wt+196608, 256, 0,   k,   nullptr, 1.f,    2);
    gemm_conv<0><<<ggrid, 256>>>(noisy, nullptr, wt+262144,256, 256, v,   nullptr, 1.f,    2);

    size_t smem = (size_t)SM_TOT * sizeof(float);   // 131,968 B
    cudaFuncSetAttribute(attn_kernel,
                         cudaFuncAttributeMaxDynamicSharedMemorySize, (int)smem);
    attn_kernel<<<dim3(NB * NB, HEADS, BATCH), 512, smem>>>(q, k, v, rel_h, rel_w, out);
}

// round 9
// speedup vs baseline: 1.1095x; 1.0645x over previous
#include <cuda_runtime.h>
#include <cstdint>

#define CH   256
#define IMG  128
#define HW   (IMG*IMG)
#define BATCH 4
#define HEADS 4
#define NB   16
#define BLK  8
#define HALO 3

typedef unsigned long long ull;

__device__ __forceinline__ ull pack2(float lo, float hi) {
    ull r; asm("mov.b64 %0, {%1,%2};" : "=l"(r) : "f"(lo), "f"(hi)); return r;
}
__device__ __forceinline__ ull pack2b(float v) { return pack2(v, v); }
__device__ __forceinline__ void fma2(ull& d, ull a, ull b) {
    asm("fma.rn.f32x2 %0, %1, %2, %0;" : "+l"(d) : "l"(a), "l"(b));
}
__device__ __forceinline__ void unpack2(ull v, float& lo, float& hi) {
    asm("mov.b64 {%0,%1}, %2;" : "=f"(lo), "=f"(hi) : "l"(v));
}
__device__ __forceinline__ float tf32r(float x) {
    uint32_t r; asm("cvt.rna.tf32.f32 %0, %1;" : "=r"(r) : "f"(x));
    return __uint_as_float(r);
}
__device__ __forceinline__ void mma8(float* d, uint32_t a0, uint32_t a1,
                                     uint32_t a2, uint32_t a3,
                                     uint32_t b0, uint32_t b1) {
    asm("mma.sync.aligned.m16n8k8.row.col.f32.tf32.tf32.f32 "
        "{%0,%1,%2,%3},{%4,%5,%6,%7},{%8,%9},{%0,%1,%2,%3};"
        : "+f"(d[0]), "+f"(d[1]), "+f"(d[2]), "+f"(d[3])
        : "r"(a0), "r"(a1), "r"(a2), "r"(a3), "r"(b0), "r"(b1));
}

// naux c-major [b][c][p]; q/k/v pixel-major [b][p][256]; wt = wq/wk/wv transposed.
__device__ float g_naux[(long)BATCH*CH*HW];
__device__ float g_q   [(long)BATCH*HW*CH];
__device__ float g_k   [(long)BATCH*HW*CH];
__device__ float g_v   [(long)BATCH*HW*CH];
__device__ float g_wt  [3*256*256];

__global__ void transpose_w(const float* __restrict__ wq,
                            const float* __restrict__ wk,
                            const float* __restrict__ wv,
                            float* __restrict__ wt)
{
    int t = blockIdx.x * 256 + threadIdx.x;   // 3*65536 total
    int m = t & 65535, u = t >> 16;
    int k = m >> 8, o = m & 255;
    const float* s = (u == 0) ? wq : (u == 1) ? wk : wv;
    wt[t] = s[o * 256 + k];
}

// ---------------------------------------------------------------------------
// gemm_cm: C[o][p] c-major out. A = W[o][k] row-major, B = X c-major (concat).
// Proven R4 kernel (f32x2, double-buffered).
// ---------------------------------------------------------------------------
__global__ __launch_bounds__(256, 2)
void gemm_cm(const float* __restrict__ A,
             const float* __restrict__ B0,
             const float* __restrict__ B1,
             int K, int K0,
             float* __restrict__ C,
             const float* __restrict__ bias)
{
    const int tid = threadIdx.x;
    const int b   = blockIdx.z;
    const int n0  = blockIdx.x * 128;
    const int m0  = blockIdx.y * 128;
    const long boff = (long)b * CH * HW;
    const float* Bb0 = B0 + boff;
    const float* Bb1 = B1 + boff;
    float* Cb = C + boff;

    __shared__ float As[2][16][132];
    __shared__ float Bs[2][16][128];

    const int ty8 = (tid >> 4) * 8;
    const int tx8 = (tid & 15) * 8;
    const int arow0 = tid >> 2, acol = (tid & 3) * 4;
    const int brow0 = tid >> 5, bcol = (tid & 31) * 4;

    ull acc[8][4];
#pragma unroll
    for (int i = 0; i < 8; i++)
#pragma unroll
        for (int q = 0; q < 4; q++) acc[i][q] = 0ull;

    const int ntiles = K / 16;
    float4 ar[2], br[2];

    auto loadAB = [&](int kb) {
#pragma unroll
        for (int p = 0; p < 2; p++)
            ar[p] = *(const float4*)&A[(long)(m0 + p * 64 + arow0) * K + kb + acol];
#pragma unroll
        for (int p = 0; p < 2; p++) {
            int kr = kb + p * 8 + brow0;
            const float* src = (kr < K0) ? (Bb0 + (long)kr * HW)
                                         : (Bb1 + (long)(kr - K0) * HW);
            br[p] = *(const float4*)&src[n0 + bcol];
        }
    };
    auto storeAB = [&](int buf) {
#pragma unroll
        for (int p = 0; p < 2; p++) {
            int row = p * 64 + arow0;
            As[buf][acol + 0][row] = ar[p].x;
            As[buf][acol + 1][row] = ar[p].y;
            As[buf][acol + 2][row] = ar[p].z;
            As[buf][acol + 3][row] = ar[p].w;
        }
#pragma unroll
        for (int p = 0; p < 2; p++)
            *(float4*)&Bs[buf][p * 8 + brow0][bcol] = br[p];
    };

    loadAB(0); storeAB(0);
    __syncthreads();

    for (int kt = 0; kt < ntiles; kt++) {
        const int cur = kt & 1, nxt = cur ^ 1;
        if (kt + 1 < ntiles) loadAB((kt + 1) * 16);
#pragma unroll
        for (int kk = 0; kk < 16; kk++) {
            float4 a0 = *(const float4*)&As[cur][kk][ty8];
            float4 a1 = *(const float4*)&As[cur][kk][ty8 + 4];
            float4 b0 = *(const float4*)&Bs[cur][kk][tx8];
            float4 b1 = *(const float4*)&Bs[cur][kk][tx8 + 4];
            float a[8] = {a0.x,a0.y,a0.z,a0.w,a1.x,a1.y,a1.z,a1.w};
            ull b2[4] = {pack2(b0.x,b0.y), pack2(b0.z,b0.w),
                         pack2(b1.x,b1.y), pack2(b1.z,b1.w)};
#pragma unroll
            for (int i = 0; i < 8; i++) {
                ull ai = pack2b(a[i]);
#pragma unroll
                for (int q = 0; q < 4; q++) fma2(acc[i][q], ai, b2[q]);
            }
        }
        if (kt + 1 < ntiles) { storeAB(nxt); __syncthreads(); }
    }

#pragma unroll
    for (int i = 0; i < 8; i++) {
        int o = m0 + ty8 + i;
        float bi = bias[o];
        float c[8];
#pragma unroll
        for (int q = 0; q < 4; q++) unpack2(acc[i][q], c[2*q], c[2*q+1]);
#pragma unroll
        for (int j = 0; j < 8; j++) c[j] = fmaxf(c[j] + bi, 0.f);
        float* dst = &Cb[(long)o * HW + n0 + tx8];
        *(float4*)&dst[0] = make_float4(c[0], c[1], c[2], c[3]);
        *(float4*)&dst[4] = make_float4(c[4], c[5], c[6], c[7]);
    }
}

// ---------------------------------------------------------------------------
// gemm_pm: C[p][n] pixel-major out. X c-major (coalesced rows into As[k][p]),
// Wt[k][n] pre-transposed weights. acc = [pixel][channel]. f32x2.
// ---------------------------------------------------------------------------
__global__ __launch_bounds__(256, 2)
void gemm_pm(const float* __restrict__ X,
             const float* __restrict__ Wt,
             float* __restrict__ C,
             float scale)
{
    const int tid = threadIdx.x;
    const int b   = blockIdx.z;
    const int m0  = blockIdx.x * 128;   // pixels
    const int n0  = blockIdx.y * 128;   // channels
    const long boff = (long)b * CH * HW;
    const float* Xb = X + boff;
    float* Cb = C + boff;

    __shared__ float As[2][16][132];
    __shared__ float Bs[2][16][128];

    const int ty8 = (tid >> 4) * 8;     // pixel frag
    const int tx8 = (tid & 15) * 8;     // channel frag
    const int akk = tid >> 4, amq = (tid & 15) * 8;
    const int brow0 = tid >> 5, bcol = (tid & 31) * 4;

    ull acc[8][4];
#pragma unroll
    for (int i = 0; i < 8; i++)
#pragma unroll
        for (int q = 0; q < 4; q++) acc[i][q] = 0ull;

    const int ntiles = 256 / 16;
    float4 ar[2], br[2];

    auto loadAB = [&](int kb) {
        const float* s = Xb + (long)(kb + akk) * HW + m0 + amq;
        ar[0] = *(const float4*)&s[0];
        ar[1] = *(const float4*)&s[4];
#pragma unroll
        for (int p = 0; p < 2; p++)
            br[p] = *(const float4*)&Wt[(long)(kb + p * 8 + brow0) * 256 + n0 + bcol];
    };
    auto storeAB = [&](int buf) {
        *(float4*)&As[buf][akk][amq]     = ar[0];
        *(float4*)&As[buf][akk][amq + 4] = ar[1];
#pragma unroll
        for (int p = 0; p < 2; p++)
            *(float4*)&Bs[buf][p * 8 + brow0][bcol] = br[p];
    };

    loadAB(0); storeAB(0);
    __syncthreads();

    for (int kt = 0; kt < ntiles; kt++) {
        const int cur = kt & 1, nxt = cur ^ 1;
        if (kt + 1 < ntiles) loadAB((kt + 1) * 16);
#pragma unroll
        for (int kk = 0; kk < 16; kk++) {
            float4 a0 = *(const float4*)&As[cur][kk][ty8];
            float4 a1 = *(const float4*)&As[cur][kk][ty8 + 4];
            float4 b0 = *(const float4*)&Bs[cur][kk][tx8];
            float4 b1 = *(const float4*)&Bs[cur][kk][tx8 + 4];
            float a[8] = {a0.x,a0.y,a0.z,a0.w,a1.x,a1.y,a1.z,a1.w};
            ull b2[4] = {pack2(b0.x,b0.y), pack2(b0.z,b0.w),
                         pack2(b1.x,b1.y), pack2(b1.z,b1.w)};
#pragma unroll
            for (int i = 0; i < 8; i++) {
                ull ai = pack2b(a[i]);
#pragma unroll
                for (int q = 0; q < 4; q++) fma2(acc[i][q], ai, b2[q]);
            }
        }
        if (kt + 1 < ntiles) { storeAB(nxt); __syncthreads(); }
    }

#pragma unroll
    for (int i = 0; i < 8; i++) {
        float c[8];
#pragma unroll
        for (int q = 0; q < 4; q++) unpack2(acc[i][q], c[2*q], c[2*q+1]);
#pragma unroll
        for (int j = 0; j < 8; j++) c[j] *= scale;
        float* dst = &Cb[(long)(m0 + ty8 + i) * 256 + n0 + tx8];
        *(float4*)&dst[0] = make_float4(c[0], c[1], c[2], c[3]);
        *(float4*)&dst[4] = make_float4(c[4], c[5], c[6], c[7]);
    }
}

// ---------------------------------------------------------------------------
// Halo attention (pixel-major) — unchanged from R8.
//   KW @0 [200][68] (rows 196-199 zero)   } overlay: simT[200][72], OT[64][68]
//   QI @13600 [64][68]
//   VJ @17952 [200][72] (rows 196-199 zero)
//   RED @32352 [8][64], MX @32864, INV @32928; TOT 32992
// ---------------------------------------------------------------------------
#define KW_OFF 0
#define KW_STR 68
#define QI_OFF 13600
#define QI_STR 68
#define ST_OFF 0
#define ST_STR 72
#define VJ_OFF 17952
#define VJ_STR 72
#define OT_OFF 0
#define OT_STR 68
#define RED_OFF 32352
#define MX_OFF 32864
#define INV_OFF 32928
#define SM_TOT 32992

__global__ __launch_bounds__(512, 1)
void attn_kernel(const float* __restrict__ gq, const float* __restrict__ gk,
                 const float* __restrict__ gv, const float* __restrict__ relh,
                 const float* __restrict__ relw, float* __restrict__ out)
{
    extern __shared__ float sm[];
    const int tid  = threadIdx.x;
    const int lane = tid & 31, w = tid >> 5;
    const int gid  = lane >> 2, tig = lane & 3;
    const int by = blockIdx.x >> 4, bx = blockIdx.x & 15;
    const int h = blockIdx.y, b = blockIdx.z;
    const int y0 = by * BLK, x0 = bx * BLK;
    const long qbase = (long)b * HW * 256 + h * 64;
    const long obase = ((long)b * CH + h * 64) * HW;

    if (tid < 272)      sm[KW_OFF + 196 * KW_STR + tid] = 0.f;
    else if (tid < 560) sm[VJ_OFF + 196 * VJ_STR + (tid - 272)] = 0.f;

    if (tid < 256) {
        int px = tid >> 2, quad = tid & 3;
        int p = (y0 + (px >> 3)) * IMG + x0 + (px & 7);
        const float* src = gq + qbase + (long)p * 256 + quad * 16;
        float* dst = &sm[QI_OFF + px * QI_STR + quad * 16];
#pragma unroll
        for (int f = 0; f < 4; f++) {
            float4 v = *(const float4*)(src + f * 4);
            *(float4*)&dst[f * 4] = make_float4(tf32r(v.x), tf32r(v.y),
                                                tf32r(v.z), tf32r(v.w));
        }
    }
    for (int u = tid; u < 1568; u += 512) {
        int isV = u >= 784;
        int e = isV ? u - 784 : u;
        int j = e >> 2, quad = e & 3;
        int iw = j / 14, jw = j - iw * 14;
        int yw = y0 - HALO + iw, xw = x0 - HALO + jw;
        bool valid = ((unsigned)yw < IMG) && ((unsigned)xw < IMG);
        int p = valid ? (yw * IMG + xw) : 0;
        if (!isV) {
            const float* src  = gk + qbase + (long)p * 256 + quad * 16;
            const float* bsrc = (quad < 2) ? (relh + iw * 32 + quad * 16)
                                           : (relw + jw * 32 + (quad - 2) * 16);
            float* dst = &sm[KW_OFF + j * KW_STR + quad * 16];
#pragma unroll
            for (int f = 0; f < 4; f++) {
                float4 bv = *(const float4*)(bsrc + f * 4);
                float4 kv = valid ? *(const float4*)(src + f * 4)
                                  : make_float4(0.f, 0.f, 0.f, 0.f);
                *(float4*)&dst[f * 4] =
                    make_float4(tf32r(kv.x + bv.x), tf32r(kv.y + bv.y),
                                tf32r(kv.z + bv.z), tf32r(kv.w + bv.w));
            }
        } else {
            const float* src = gv + qbase + (long)p * 256 + quad * 16;
            float* dst = &sm[VJ_OFF + j * VJ_STR + quad * 16];
#pragma unroll
            for (int f = 0; f < 4; f++) {
                float4 kv = valid ? *(const float4*)(src + f * 4)
                                  : make_float4(0.f, 0.f, 0.f, 0.f);
                *(float4*)&dst[f * 4] = make_float4(tf32r(kv.x), tf32r(kv.y),
                                                    tf32r(kv.z), tf32r(kv.w));
            }
        }
    }
    __syncthreads();

    const int wm = w >> 2, wn = w & 3;
    const int mcnt   = (wm == 0) ? 4 : 3;
    const int mtile0 = (wm == 0) ? 0 : (4 + 3 * (wm - 1));
    float Cf[4][2][4];
#pragma unroll
    for (int mt = 0; mt < 4; mt++)
#pragma unroll
        for (int nt = 0; nt < 2; nt++)
#pragma unroll
            for (int q = 0; q < 4; q++) Cf[mt][nt][q] = 0.f;

#pragma unroll
    for (int ks = 0; ks < 8; ks++) {
        const int c0 = ks * 8;
        uint32_t Bf[2][2];
#pragma unroll
        for (int nt = 0; nt < 2; nt++) {
            int n = wn * 16 + nt * 8 + gid;
            Bf[nt][0] = __float_as_uint(sm[QI_OFF + n * QI_STR + c0 + tig]);
            Bf[nt][1] = __float_as_uint(sm[QI_OFF + n * QI_STR + c0 + tig + 4]);
        }
#pragma unroll
        for (int mt = 0; mt < 4; mt++) {
            if (mt < mcnt) {
                int r = (mtile0 + mt) * 16 + gid;
                uint32_t a0 = __float_as_uint(sm[KW_OFF + r       * KW_STR + c0 + tig]);
                uint32_t a1 = __float_as_uint(sm[KW_OFF + (r + 8) * KW_STR + c0 + tig]);
                uint32_t a2 = __float_as_uint(sm[KW_OFF + r       * KW_STR + c0 + tig + 4]);
                uint32_t a3 = __float_as_uint(sm[KW_OFF + (r + 8) * KW_STR + c0 + tig + 4]);
                mma8(Cf[mt][0], a0, a1, a2, a3, Bf[0][0], Bf[0][1]);
                mma8(Cf[mt][1], a0, a1, a2, a3, Bf[1][0], Bf[1][1]);
            }
        }
    }
    __syncthreads();

#pragma unroll
    for (int mt = 0; mt < 4; mt++) {
        if (mt < mcnt) {
#pragma unroll
            for (int nt = 0; nt < 2; nt++) {
                int r = (mtile0 + mt) * 16 + gid;
                int ci = wn * 16 + nt * 8 + 2 * tig;
                *(float2*)&sm[ST_OFF + r * ST_STR + ci] =
                    make_float2(Cf[mt][nt][0], Cf[mt][nt][1]);
                if (r + 8 < 200)
                    *(float2*)&sm[ST_OFF + (r + 8) * ST_STR + ci] =
                        make_float2(Cf[mt][nt][2], Cf[mt][nt][3]);
            }
        }
    }
    __syncthreads();

    {
        const int i = tid & 63, p = tid >> 6;
        const int cnt = (p < 4) ? 25 : 24;
        const int jb  = (p < 4) ? p * 25 : 100 + (p - 4) * 24;
        float m = -1e30f;
        for (int jj = 0; jj < cnt; jj++)
            m = fmaxf(m, sm[ST_OFF + (jb + jj) * ST_STR + i]);
        sm[RED_OFF + p * 64 + i] = m;
        __syncthreads();
        if (tid < 64) {
            float mm = -1e30f;
#pragma unroll
            for (int pp = 0; pp < 8; pp++)
                mm = fmaxf(mm, sm[RED_OFF + pp * 64 + tid]);
            sm[MX_OFF + tid] = mm;
        }
        __syncthreads();
        float mm = sm[MX_OFF + i];
        float s = 0.f;
        for (int jj = 0; jj < cnt; jj++) {
            float e = __expf(sm[ST_OFF + (jb + jj) * ST_STR + i] - mm);
            s += e;
            sm[ST_OFF + (jb + jj) * ST_STR + i] = tf32r(e);
        }
        sm[RED_OFF + p * 64 + i] = s;
        if (tid < 4 * ST_STR) sm[ST_OFF + 196 * ST_STR + tid] = 0.f;
        __syncthreads();
        if (tid < 64) {
            float ss = 0.f;
#pragma unroll
            for (int pp = 0; pp < 8; pp++)
                ss += sm[RED_OFF + pp * 64 + tid];
            sm[INV_OFF + tid] = 1.f / ss;
        }
        __syncthreads();
    }

    {
        const int ibase = (w >> 2) * 16;
        const int wn2 = w & 3;
        float Df[2][4];
#pragma unroll
        for (int nt = 0; nt < 2; nt++)
#pragma unroll
            for (int q = 0; q < 4; q++) Df[nt][q] = 0.f;

        for (int kt = 0; kt < 25; kt++) {
            const int j0 = kt * 8;
            uint32_t a0 = __float_as_uint(sm[ST_OFF + (j0 + tig)     * ST_STR + ibase + gid]);
            uint32_t a1 = __float_as_uint(sm[ST_OFF + (j0 + tig)     * ST_STR + ibase + gid + 8]);
            uint32_t a2 = __float_as_uint(sm[ST_OFF + (j0 + tig + 4) * ST_STR + ibase + gid]);
            uint32_t a3 = __float_as_uint(sm[ST_OFF + (j0 + tig + 4) * ST_STR + ibase + gid + 8]);
#pragma unroll
            for (int nt = 0; nt < 2; nt++) {
                int c0 = wn2 * 16 + nt * 8;
                uint32_t b0 = __float_as_uint(sm[VJ_OFF + (j0 + tig)     * VJ_STR + c0 + gid]);
                uint32_t b1 = __float_as_uint(sm[VJ_OFF + (j0 + tig + 4) * VJ_STR + c0 + gid]);
                mma8(Df[nt], a0, a1, a2, a3, b0, b1);
            }
        }
        float v0 = sm[INV_OFF + ibase + gid];
        float v1 = sm[INV_OFF + ibase + gid + 8];
        __syncthreads();

#pragma unroll
        for (int nt = 0; nt < 2; nt++) {
            int c0 = wn2 * 16 + nt * 8;
            sm[OT_OFF + (c0 + 2*tig    ) * OT_STR + ibase + gid]     = Df[nt][0] * v0;
            sm[OT_OFF + (c0 + 2*tig + 1) * OT_STR + ibase + gid]     = Df[nt][1] * v0;
            sm[OT_OFF + (c0 + 2*tig    ) * OT_STR + ibase + gid + 8] = Df[nt][2] * v1;
            sm[OT_OFF + (c0 + 2*tig + 1) * OT_STR + ibase + gid + 8] = Df[nt][3] * v1;
        }
        __syncthreads();

        int c = tid >> 3, r = tid & 7;
        float4 o0 = *(const float4*)&sm[OT_OFF + c * OT_STR + r * 8];
        float4 o1 = *(const float4*)&sm[OT_OFF + c * OT_STR + r * 8 + 4];
        float* dst = out + obase + (long)c * HW + (y0 + r) * IMG + x0;
        *(float4*)&dst[0] = o0;
        *(float4*)&dst[4] = o1;
    }
}

// ---------------------------------------------------------------------------
extern "C" void kernel_launch(void* const* d_in, const int* in_sizes, int n_in,
                              void* d_out, int out_size)
{
    const float* noisy = (const float*)d_in[0];
    const float* aux   = (const float*)d_in[1];
    const float* w_map = (const float*)d_in[2];
    const float* b_map = (const float*)d_in[3];
    const float* w_q   = (const float*)d_in[4];
    const float* w_k   = (const float*)d_in[5];
    const float* w_v   = (const float*)d_in[6];
    const float* rel_h = (const float*)d_in[7];
    const float* rel_w = (const float*)d_in[8];
    float* out = (float*)d_out;

    float *naux, *q, *k, *v, *wt;
    cudaGetSymbolAddress((void**)&naux, g_naux);
    cudaGetSymbolAddress((void**)&q,    g_q);
    cudaGetSymbolAddress((void**)&k,    g_k);
    cudaGetSymbolAddress((void**)&v,    g_v);
    cudaGetSymbolAddress((void**)&wt,   g_wt);

    transpose_w<<<768, 256>>>(w_q, w_k, w_v, wt);

    dim3 ggrid(HW / 128, CH / 128, BATCH);
    // naux (c-major) = relu(Wmap @ [noisy;aux] + b)
    gemm_cm<<<ggrid, 256>>>(w_map, noisy, aux, 512, 256, naux, b_map);
    // q/k/v pixel-major
    gemm_pm<<<ggrid, 256>>>(naux,  wt,           q, 0.125f);
    gemm_pm<<<ggrid, 256>>>(naux,  wt + 65536,   k, 1.f);
    gemm_pm<<<ggrid, 256>>>(noisy, wt + 131072,  v, 1.f);

    size_t smem = (size_t)SM_TOT * sizeof(float);
    cudaFuncSetAttribute(attn_kernel,
                         cudaFuncAttributeMaxDynamicSharedMemorySize, (int)smem);
    attn_kernel<<<dim3(NB * NB, HEADS, BATCH), 512, smem>>>(q, k, v, rel_h, rel_w, out);
}

// round 11
// speedup vs baseline: 1.2041x; 1.0853x over previous
#include <cuda_runtime.h>
#include <cstdint>

#define CH   256
#define IMG  128
#define HW   (IMG*IMG)
#define BATCH 4
#define HEADS 4
#define NB   16
#define BLK  8
#define HALO 3

__device__ __forceinline__ float tf32r(float x) {
    uint32_t r; asm("cvt.rna.tf32.f32 %0, %1;" : "=r"(r) : "f"(x));
    return __uint_as_float(r);
}
__device__ __forceinline__ void mma8(float* d, uint32_t a0, uint32_t a1,
                                     uint32_t a2, uint32_t a3,
                                     uint32_t b0, uint32_t b1) {
    asm("mma.sync.aligned.m16n8k8.row.col.f32.tf32.tf32.f32 "
        "{%0,%1,%2,%3},{%4,%5,%6,%7},{%8,%9},{%0,%1,%2,%3};"
        : "+f"(d[0]), "+f"(d[1]), "+f"(d[2]), "+f"(d[3])
        : "r"(a0), "r"(a1), "r"(a2), "r"(a3), "r"(b0), "r"(b1));
}
// split: hi = tf32(x), lo = tf32(x - hi)
__device__ __forceinline__ void tsplit(float x, uint32_t& hi, uint32_t& lo) {
    float h = tf32r(x);
    hi = __float_as_uint(h);
    lo = __float_as_uint(tf32r(x - h));
}

// naux c-major [b][c][p]; q/k/v pixel-major [b][p][256]; wt = transposed weights.
__device__ float g_naux[(long)BATCH*CH*HW];
__device__ float g_q   [(long)BATCH*HW*CH];
__device__ float g_k   [(long)BATCH*HW*CH];
__device__ float g_v   [(long)BATCH*HW*CH];
__device__ float g_wt  [512*256 + 3*256*256];   // wmapT, wqT, wkT, wvT

__global__ void transpose_w(const float* __restrict__ wm,
                            const float* __restrict__ wq,
                            const float* __restrict__ wk,
                            const float* __restrict__ wv,
                            float* __restrict__ wt)
{
    int t = blockIdx.x * 256 + threadIdx.x;     // 1280 blocks = 327680
    if (t < 131072)      { int k = t >> 8, o = t & 255; wt[t] = wm[o * 512 + k]; }
    else if (t < 196608) { int u = t - 131072; wt[t] = wq[(u & 255) * 256 + (u >> 8)]; }
    else if (t < 262144) { int u = t - 196608; wt[t] = wk[(u & 255) * 256 + (u >> 8)]; }
    else if (t < 327680) { int u = t - 262144; wt[t] = wv[(u & 255) * 256 + (u >> 8)]; }
}

// ---------------------------------------------------------------------------
// Split-tf32 tensor-core conv GEMM (fp32-accurate).
// D[m][n] = sum_k P[k][m] * Q[k][n]; P,Q k-major (ldP/ldQ); Q concat (K0).
// mswap selects block->tile mapping. mode 0: relu(+bias[m]); 1: *scale; 2: plain.
// ---------------------------------------------------------------------------
__global__ __launch_bounds__(256, 2)
void gemm_t(const float* __restrict__ P,  long pB, int ldP,
            const float* __restrict__ Q0, const float* __restrict__ Q1,
            long qB, int ldQ, int K, int K0,
            float* __restrict__ C, int ldc,
            const float* __restrict__ bias, float scale, int mode, int mswap)
{
    const int tid  = threadIdx.x;
    const int lane = tid & 31, w = tid >> 5;
    const int gid  = lane >> 2, tig = lane & 3;
    const int b    = blockIdx.z;
    const int m0   = (mswap ? blockIdx.x : blockIdx.y) * 128;
    const int n0   = (mswap ? blockIdx.y : blockIdx.x) * 128;
    const float* Pb  = P  + (long)b * pB;
    const float* Q0b = Q0 + (long)b * qB;
    const float* Q1b = Q1 ? (Q1 + (long)b * qB) : nullptr;
    float* Cb = C + (long)b * CH * HW;

    __shared__ float Ps[2][16][132];
    __shared__ float Qs[2][16][132];

    const int lrow = tid >> 4;            // k within tile
    const int lcol = (tid & 15) * 8;

    const int wm = w >> 2, wn = w & 3;    // 2 x 4 warp grid
    float Cf[4][4][4];
#pragma unroll
    for (int mt = 0; mt < 4; mt++)
#pragma unroll
        for (int nt = 0; nt < 4; nt++)
#pragma unroll
            for (int q = 0; q < 4; q++) Cf[mt][nt][q] = 0.f;

    const int ntiles = K / 16;
    float4 pr0, pr1, qr0, qr1;

    auto loadT = [&](int kb) {
        const float* sp = Pb + (long)(kb + lrow) * ldP + m0 + lcol;
        pr0 = *(const float4*)&sp[0];
        pr1 = *(const float4*)&sp[4];
        int kr = kb + lrow;
        const float* sq = (kr < K0) ? (Q0b + (long)kr * ldQ)
                                    : (Q1b + (long)(kr - K0) * ldQ);
        qr0 = *(const float4*)&sq[n0 + lcol];
        qr1 = *(const float4*)&sq[n0 + lcol + 4];
    };
    auto storeT = [&](int buf) {
        *(float4*)&Ps[buf][lrow][lcol]     = pr0;
        *(float4*)&Ps[buf][lrow][lcol + 4] = pr1;
        *(float4*)&Qs[buf][lrow][lcol]     = qr0;
        *(float4*)&Qs[buf][lrow][lcol + 4] = qr1;
    };

    loadT(0); storeT(0);
    __syncthreads();

    for (int kt = 0; kt < ntiles; kt++) {
        const int cur = kt & 1, nxt = cur ^ 1;
        if (kt + 1 < ntiles) loadT((kt + 1) * 16);

#pragma unroll
        for (int k8 = 0; k8 < 16; k8 += 8) {
            // B fragments hi/lo (once per k8)
            uint32_t bhi[4][2], blo[4][2];
#pragma unroll
            for (int nt = 0; nt < 4; nt++) {
                int n = wn * 32 + nt * 8 + gid;
                tsplit(Qs[cur][k8 + tig][n],     bhi[nt][0], blo[nt][0]);
                tsplit(Qs[cur][k8 + tig + 4][n], bhi[nt][1], blo[nt][1]);
            }
#pragma unroll
            for (int mt = 0; mt < 4; mt++) {
                int m = wm * 64 + mt * 16 + gid;
                uint32_t ah[4], al[4];
                tsplit(Ps[cur][k8 + tig][m],         ah[0], al[0]);
                tsplit(Ps[cur][k8 + tig][m + 8],     ah[1], al[1]);
                tsplit(Ps[cur][k8 + tig + 4][m],     ah[2], al[2]);
                tsplit(Ps[cur][k8 + tig + 4][m + 8], ah[3], al[3]);
#pragma unroll
                for (int nt = 0; nt < 4; nt++) {
                    mma8(Cf[mt][nt], ah[0], ah[1], ah[2], ah[3], bhi[nt][0], bhi[nt][1]);
                    mma8(Cf[mt][nt], ah[0], ah[1], ah[2], ah[3], blo[nt][0], blo[nt][1]);
                    mma8(Cf[mt][nt], al[0], al[1], al[2], al[3], bhi[nt][0], bhi[nt][1]);
                }
            }
        }
        if (kt + 1 < ntiles) { __syncthreads(); storeT(nxt); __syncthreads(); }
    }

    // epilogue
#pragma unroll
    for (int mt = 0; mt < 4; mt++) {
        int r0 = m0 + wm * 64 + mt * 16 + gid;
        float bi0 = 0.f, bi1 = 0.f;
        if (mode == 0) { bi0 = bias[r0]; bi1 = bias[r0 + 8]; }
#pragma unroll
        for (int nt = 0; nt < 4; nt++) {
            int cc = n0 + wn * 32 + nt * 8 + 2 * tig;
            float d0 = Cf[mt][nt][0], d1 = Cf[mt][nt][1];
            float d2 = Cf[mt][nt][2], d3 = Cf[mt][nt][3];
            if (mode == 0) {
                d0 = fmaxf(d0 + bi0, 0.f); d1 = fmaxf(d1 + bi0, 0.f);
                d2 = fmaxf(d2 + bi1, 0.f); d3 = fmaxf(d3 + bi1, 0.f);
            } else if (mode == 1) {
                d0 *= scale; d1 *= scale; d2 *= scale; d3 *= scale;
            }
            *(float2*)&Cb[(long)r0 * ldc + cc]       = make_float2(d0, d1);
            *(float2*)&Cb[(long)(r0 + 8) * ldc + cc] = make_float2(d2, d3);
        }
    }
}

// ---------------------------------------------------------------------------
// Halo attention (pixel-major) — unchanged from R9 (passing, 5.87e-4).
// ---------------------------------------------------------------------------
#define KW_OFF 0
#define KW_STR 68
#define QI_OFF 13600
#define QI_STR 68
#define ST_OFF 0
#define ST_STR 72
#define VJ_OFF 17952
#define VJ_STR 72
#define OT_OFF 0
#define OT_STR 68
#define RED_OFF 32352
#define MX_OFF 32864
#define INV_OFF 32928
#define SM_TOT 32992

__global__ __launch_bounds__(512, 1)
void attn_kernel(const float* __restrict__ gq, const float* __restrict__ gk,
                 const float* __restrict__ gv, const float* __restrict__ relh,
                 const float* __restrict__ relw, float* __restrict__ out)
{
    extern __shared__ float sm[];
    const int tid  = threadIdx.x;
    const int lane = tid & 31, w = tid >> 5;
    const int gid  = lane >> 2, tig = lane & 3;
    const int by = blockIdx.x >> 4, bx = blockIdx.x & 15;
    const int h = blockIdx.y, b = blockIdx.z;
    const int y0 = by * BLK, x0 = bx * BLK;
    const long qbase = (long)b * HW * 256 + h * 64;
    const long obase = ((long)b * CH + h * 64) * HW;

    if (tid < 272)      sm[KW_OFF + 196 * KW_STR + tid] = 0.f;
    else if (tid < 560) sm[VJ_OFF + 196 * VJ_STR + (tid - 272)] = 0.f;

    if (tid < 256) {
        int px = tid >> 2, quad = tid & 3;
        int p = (y0 + (px >> 3)) * IMG + x0 + (px & 7);
        const float* src = gq + qbase + (long)p * 256 + quad * 16;
        float* dst = &sm[QI_OFF + px * QI_STR + quad * 16];
#pragma unroll
        for (int f = 0; f < 4; f++) {
            float4 v = *(const float4*)(src + f * 4);
            *(float4*)&dst[f * 4] = make_float4(tf32r(v.x), tf32r(v.y),
                                                tf32r(v.z), tf32r(v.w));
        }
    }
    for (int u = tid; u < 1568; u += 512) {
        int isV = u >= 784;
        int e = isV ? u - 784 : u;
        int j = e >> 2, quad = e & 3;
        int iw = j / 14, jw = j - iw * 14;
        int yw = y0 - HALO + iw, xw = x0 - HALO + jw;
        bool valid = ((unsigned)yw < IMG) && ((unsigned)xw < IMG);
        int p = valid ? (yw * IMG + xw) : 0;
        if (!isV) {
            const float* src  = gk + qbase + (long)p * 256 + quad * 16;
            const float* bsrc = (quad < 2) ? (relh + iw * 32 + quad * 16)
                                           : (relw + jw * 32 + (quad - 2) * 16);
            float* dst = &sm[KW_OFF + j * KW_STR + quad * 16];
#pragma unroll
            for (int f = 0; f < 4; f++) {
                float4 bv = *(const float4*)(bsrc + f * 4);
                float4 kv = valid ? *(const float4*)(src + f * 4)
                                  : make_float4(0.f, 0.f, 0.f, 0.f);
                *(float4*)&dst[f * 4] =
                    make_float4(tf32r(kv.x + bv.x), tf32r(kv.y + bv.y),
                                tf32r(kv.z + bv.z), tf32r(kv.w + bv.w));
            }
        } else {
            const float* src = gv + qbase + (long)p * 256 + quad * 16;
            float* dst = &sm[VJ_OFF + j * VJ_STR + quad * 16];
#pragma unroll
            for (int f = 0; f < 4; f++) {
                float4 kv = valid ? *(const float4*)(src + f * 4)
                                  : make_float4(0.f, 0.f, 0.f, 0.f);
                *(float4*)&dst[f * 4] = make_float4(tf32r(kv.x), tf32r(kv.y),
                                                    tf32r(kv.z), tf32r(kv.w));
            }
        }
    }
    __syncthreads();

    const int wm = w >> 2, wn = w & 3;
    const int mcnt   = (wm == 0) ? 4 : 3;
    const int mtile0 = (wm == 0) ? 0 : (4 + 3 * (wm - 1));
    float Cf[4][2][4];
#pragma unroll
    for (int mt = 0; mt < 4; mt++)
#pragma unroll
        for (int nt = 0; nt < 2; nt++)
#pragma unroll
            for (int q = 0; q < 4; q++) Cf[mt][nt][q] = 0.f;

#pragma unroll
    for (int ks = 0; ks < 8; ks++) {
        const int c0 = ks * 8;
        uint32_t Bf[2][2];
#pragma unroll
        for (int nt = 0; nt < 2; nt++) {
            int n = wn * 16 + nt * 8 + gid;
            Bf[nt][0] = __float_as_uint(sm[QI_OFF + n * QI_STR + c0 + tig]);
            Bf[nt][1] = __float_as_uint(sm[QI_OFF + n * QI_STR + c0 + tig + 4]);
        }
#pragma unroll
        for (int mt = 0; mt < 4; mt++) {
            if (mt < mcnt) {
                int r = (mtile0 + mt) * 16 + gid;
                uint32_t a0 = __float_as_uint(sm[KW_OFF + r       * KW_STR + c0 + tig]);
                uint32_t a1 = __float_as_uint(sm[KW_OFF + (r + 8) * KW_STR + c0 + tig]);
                uint32_t a2 = __float_as_uint(sm[KW_OFF + r       * KW_STR + c0 + tig + 4]);
                uint32_t a3 = __float_as_uint(sm[KW_OFF + (r + 8) * KW_STR + c0 + tig + 4]);
                mma8(Cf[mt][0], a0, a1, a2, a3, Bf[0][0], Bf[0][1]);
                mma8(Cf[mt][1], a0, a1, a2, a3, Bf[1][0], Bf[1][1]);
            }
        }
    }
    __syncthreads();

#pragma unroll
    for (int mt = 0; mt < 4; mt++) {
        if (mt < mcnt) {
#pragma unroll
            for (int nt = 0; nt < 2; nt++) {
                int r = (mtile0 + mt) * 16 + gid;
                int ci = wn * 16 + nt * 8 + 2 * tig;
                *(float2*)&sm[ST_OFF + r * ST_STR + ci] =
                    make_float2(Cf[mt][nt][0], Cf[mt][nt][1]);
                if (r + 8 < 200)
                    *(float2*)&sm[ST_OFF + (r + 8) * ST_STR + ci] =
                        make_float2(Cf[mt][nt][2], Cf[mt][nt][3]);
            }
        }
    }
    __syncthreads();

    {
        const int i = tid & 63, p = tid >> 6;
        const int cnt = (p < 4) ? 25 : 24;
        const int jb  = (p < 4) ? p * 25 : 100 + (p - 4) * 24;
        float m = -1e30f;
        for (int jj = 0; jj < cnt; jj++)
            m = fmaxf(m, sm[ST_OFF + (jb + jj) * ST_STR + i]);
        sm[RED_OFF + p * 64 + i] = m;
        __syncthreads();
        if (tid < 64) {
            float mm = -1e30f;
#pragma unroll
            for (int pp = 0; pp < 8; pp++)
                mm = fmaxf(mm, sm[RED_OFF + pp * 64 + tid]);
            sm[MX_OFF + tid] = mm;
        }
        __syncthreads();
        float mm = sm[MX_OFF + i];
        float s = 0.f;
        for (int jj = 0; jj < cnt; jj++) {
            float e = __expf(sm[ST_OFF + (jb + jj) * ST_STR + i] - mm);
            s += e;
            sm[ST_OFF + (jb + jj) * ST_STR + i] = tf32r(e);
        }
        sm[RED_OFF + p * 64 + i] = s;
        if (tid < 4 * ST_STR) sm[ST_OFF + 196 * ST_STR + tid] = 0.f;
        __syncthreads();
        if (tid < 64) {
            float ss = 0.f;
#pragma unroll
            for (int pp = 0; pp < 8; pp++)
                ss += sm[RED_OFF + pp * 64 + tid];
            sm[INV_OFF + tid] = 1.f / ss;
        }
        __syncthreads();
    }

    {
        const int ibase = (w >> 2) * 16;
        const int wn2 = w & 3;
        float Df[2][4];
#pragma unroll
        for (int nt = 0; nt < 2; nt++)
#pragma unroll
            for (int q = 0; q < 4; q++) Df[nt][q] = 0.f;

        for (int kt = 0; kt < 25; kt++) {
            const int j0 = kt * 8;
            uint32_t a0 = __float_as_uint(sm[ST_OFF + (j0 + tig)     * ST_STR + ibase + gid]);
            uint32_t a1 = __float_as_uint(sm[ST_OFF + (j0 + tig)     * ST_STR + ibase + gid + 8]);
            uint32_t a2 = __float_as_uint(sm[ST_OFF + (j0 + tig + 4) * ST_STR + ibase + gid]);
            uint32_t a3 = __float_as_uint(sm[ST_OFF + (j0 + tig + 4) * ST_STR + ibase + gid + 8]);
#pragma unroll
            for (int nt = 0; nt < 2; nt++) {
                int c0 = wn2 * 16 + nt * 8;
                uint32_t b0 = __float_as_uint(sm[VJ_OFF + (j0 + tig)     * VJ_STR + c0 + gid]);
                uint32_t b1 = __float_as_uint(sm[VJ_OFF + (j0 + tig + 4) * VJ_STR + c0 + gid]);
                mma8(Df[nt], a0, a1, a2, a3, b0, b1);
            }
        }
        float v0 = sm[INV_OFF + ibase + gid];
        float v1 = sm[INV_OFF + ibase + gid + 8];
        __syncthreads();

#pragma unroll
        for (int nt = 0; nt < 2; nt++) {
            int c0 = wn2 * 16 + nt * 8;
            sm[OT_OFF + (c0 + 2*tig    ) * OT_STR + ibase + gid]     = Df[nt][0] * v0;
            sm[OT_OFF + (c0 + 2*tig + 1) * OT_STR + ibase + gid]     = Df[nt][1] * v0;
            sm[OT_OFF + (c0 + 2*tig    ) * OT_STR + ibase + gid + 8] = Df[nt][2] * v1;
            sm[OT_OFF + (c0 + 2*tig + 1) * OT_STR + ibase + gid + 8] = Df[nt][3] * v1;
        }
        __syncthreads();

        int c = tid >> 3, r = tid & 7;
        float4 o0 = *(const float4*)&sm[OT_OFF + c * OT_STR + r * 8];
        float4 o1 = *(const float4*)&sm[OT_OFF + c * OT_STR + r * 8 + 4];
        float* dst = out + obase + (long)c * HW + (y0 + r) * IMG + x0;
        *(float4*)&dst[0] = o0;
        *(float4*)&dst[4] = o1;
    }
}

// ---------------------------------------------------------------------------
extern "C" void kernel_launch(void* const* d_in, const int* in_sizes, int n_in,
                              void* d_out, int out_size)
{
    const float* noisy = (const float*)d_in[0];
    const float* aux   = (const float*)d_in[1];
    const float* w_map = (const float*)d_in[2];
    const float* b_map = (const float*)d_in[3];
    const float* w_q   = (const float*)d_in[4];
    const float* w_k   = (const float*)d_in[5];
    const float* w_v   = (const float*)d_in[6];
    const float* rel_h = (const float*)d_in[7];
    const float* rel_w = (const float*)d_in[8];
    float* out = (float*)d_out;

    float *naux, *q, *k, *v, *wt;
    cudaGetSymbolAddress((void**)&naux, g_naux);
    cudaGetSymbolAddress((void**)&q,    g_q);
    cudaGetSymbolAddress((void**)&k,    g_k);
    cudaGetSymbolAddress((void**)&v,    g_v);
    cudaGetSymbolAddress((void**)&wt,   g_wt);

    transpose_w<<<1280, 256>>>(w_map, w_q, w_k, w_v, wt);

    const long XB = (long)CH * HW;
    dim3 ggrid(128, 2, BATCH);
    // naux c-major: m=och (P = wmapT), n=pixels (Q = noisy|aux c-major)
    gemm_t<<<ggrid, 256>>>(wt, 0, 256, noisy, aux, XB, HW, 512, 256,
                           naux, HW, b_map, 1.f, 0, 0);
    // q/k/v pixel-major: m=pixels (P = X c-major), n=och (Q = wT)
    gemm_t<<<ggrid, 256>>>(naux,  XB, HW, wt + 131072, nullptr, 0, 256, 256, 256,
                           q, 256, nullptr, 0.125f, 1, 1);
    gemm_t<<<ggrid, 256>>>(naux,  XB, HW, wt + 196608, nullptr, 0, 256, 256, 256,
                           k, 256, nullptr, 1.f, 2, 1);
    gemm_t<<<ggrid, 256>>>(noisy, XB, HW, wt + 262144, nullptr, 0, 256, 256, 256,
                           v, 256, nullptr, 1.f, 2, 1);

    size_t smem = (size_t)SM_TOT * sizeof(float);
    cudaFuncSetAttribute(attn_kernel,
                         cudaFuncAttributeMaxDynamicSharedMemorySize, (int)smem);
    attn_kernel<<<dim3(NB * NB, HEADS, BATCH), 512, smem>>>(q, k, v, rel_h, rel_w, out);
}

// round 12
// speedup vs baseline: 1.8615x; 1.5460x over previous
#include <cuda_runtime.h>
#include <cstdint>

#define CH   256
#define IMG  128
#define HW   (IMG*IMG)
#define BATCH 4
#define HEADS 4
#define NB   16
#define BLK  8
#define HALO 3

__device__ __forceinline__ float tf32r(float x) {
    uint32_t r; asm("cvt.rna.tf32.f32 %0, %1;" : "=r"(r) : "f"(x));
    return __uint_as_float(r);
}
__device__ __forceinline__ void mma8(float* d, uint32_t a0, uint32_t a1,
                                     uint32_t a2, uint32_t a3,
                                     uint32_t b0, uint32_t b1) {
    asm("mma.sync.aligned.m16n8k8.row.col.f32.tf32.tf32.f32 "
        "{%0,%1,%2,%3},{%4,%5,%6,%7},{%8,%9},{%0,%1,%2,%3};"
        : "+f"(d[0]), "+f"(d[1]), "+f"(d[2]), "+f"(d[3])
        : "r"(a0), "r"(a1), "r"(a2), "r"(a3), "r"(b0), "r"(b1));
}
__device__ __forceinline__ void mma16b(float* d, const uint32_t* a,
                                       uint32_t b0, uint32_t b1) {
    asm("mma.sync.aligned.m16n8k16.row.col.f32.bf16.bf16.f32 "
        "{%0,%1,%2,%3},{%4,%5,%6,%7},{%8,%9},{%0,%1,%2,%3};"
        : "+f"(d[0]), "+f"(d[1]), "+f"(d[2]), "+f"(d[3])
        : "r"(a[0]), "r"(a[1]), "r"(a[2]), "r"(a[3]), "r"(b0), "r"(b1));
}
// bf16 split of a k-pair (xe = k even, xo = k odd):
//   hi = bf16x2(xe,xo) ; lo = bf16x2(xe-hi.e, xo-hi.o)
__device__ __forceinline__ void bsplit2(float xe, float xo,
                                        uint32_t& hi, uint32_t& lo) {
    uint32_t h;
    asm("cvt.rn.bf16x2.f32 %0, %1, %2;" : "=r"(h) : "f"(xo), "f"(xe));
    float re = xe - __uint_as_float(h << 16);
    float ro = xo - __uint_as_float(h & 0xffff0000u);
    asm("cvt.rn.bf16x2.f32 %0, %1, %2;" : "=r"(lo) : "f"(ro), "f"(re));
    hi = h;
}

// naux c-major [b][c][p]; q/k/v pixel-major [b][p][256]; wt = transposed weights.
__device__ float g_naux[(long)BATCH*CH*HW];
__device__ float g_q   [(long)BATCH*HW*CH];
__device__ float g_k   [(long)BATCH*HW*CH];
__device__ float g_v   [(long)BATCH*HW*CH];
__device__ float g_wt  [512*256 + 3*256*256];   // wmapT, wqT, wkT, wvT

__global__ void transpose_w(const float* __restrict__ wm,
                            const float* __restrict__ wq,
                            const float* __restrict__ wk,
                            const float* __restrict__ wv,
                            float* __restrict__ wt)
{
    int t = blockIdx.x * 256 + threadIdx.x;     // 1280 blocks = 327680
    if (t < 131072)      { int k = t >> 8, o = t & 255; wt[t] = wm[o * 512 + k]; }
    else if (t < 196608) { int u = t - 131072; wt[t] = wq[(u & 255) * 256 + (u >> 8)]; }
    else if (t < 262144) { int u = t - 196608; wt[t] = wk[(u & 255) * 256 + (u >> 8)]; }
    else if (t < 327680) { int u = t - 262144; wt[t] = wv[(u & 255) * 256 + (u >> 8)]; }
}

// ---------------------------------------------------------------------------
// Split-bf16 tensor-core conv GEMM (fp32-accurate: hi*hi + hi*lo + lo*hi).
// D[m][n] = sum_k P[k][m] * Q[k][n]; P,Q k-major (ldP/ldQ); Q concat (K0, even).
// Loader pre-splits into packed bf16x2 (k-pair major) smem arrays.
// ---------------------------------------------------------------------------
__global__ __launch_bounds__(256, 2)
void gemm_b(const float* __restrict__ P,  long pB, int ldP,
            const float* __restrict__ Q0, const float* __restrict__ Q1,
            long qB, int ldQ, int K, int K0,
            float* __restrict__ C, int ldc,
            const float* __restrict__ bias, float scale, int mode, int mswap)
{
    const int tid  = threadIdx.x;
    const int lane = tid & 31, w = tid >> 5;
    const int gid  = lane >> 2, tig = lane & 3;
    const int b    = blockIdx.z;
    const int m0   = (mswap ? blockIdx.x : blockIdx.y) * 128;
    const int n0   = (mswap ? blockIdx.y : blockIdx.x) * 128;
    const float* Pb  = P  + (long)b * pB;
    const float* Q0b = Q0 + (long)b * qB;
    const float* Q1b = Q1 ? (Q1 + (long)b * qB) : nullptr;
    float* Cb = C + (long)b * CH * HW;

    // packed bf16x2 tiles, k-pair major: [k2 0..7][col 0..127], stride 136
    __shared__ uint32_t PH[2][8][136], PL[2][8][136];
    __shared__ uint32_t QH[2][8][136], QL[2][8][136];

    // loader: threads 0-127 -> P side, 128-255 -> Q side
    const int side = tid >> 7;
    const int lt   = tid & 127;
    const int k2   = lt >> 4;           // 0..7 (k-pair within 16-row tile)
    const int mq   = (lt & 15) * 8;     // 0..120

    const int wm = w >> 2, wn = w & 3;  // 2 x 4 warp grid
    float Cf[4][4][4];
#pragma unroll
    for (int mt = 0; mt < 4; mt++)
#pragma unroll
        for (int nt = 0; nt < 4; nt++)
#pragma unroll
            for (int q = 0; q < 4; q++) Cf[mt][nt][q] = 0.f;

    const int ntiles = K / 16;
    float4 e0, e1, o0, o1;   // even-k row (8 cols), odd-k row

    auto loadT = [&](int kb) {
        int kr = kb + 2 * k2;
        if (side == 0) {
            const float* s0 = Pb + (long)kr * ldP + m0 + mq;
            const float* s1 = s0 + ldP;
            e0 = *(const float4*)&s0[0]; e1 = *(const float4*)&s0[4];
            o0 = *(const float4*)&s1[0]; o1 = *(const float4*)&s1[4];
        } else {
            const float* s0 = ((kr     < K0) ? (Q0b + (long)kr * ldQ)
                                             : (Q1b + (long)(kr - K0) * ldQ)) + n0 + mq;
            const float* s1 = ((kr + 1 < K0) ? (Q0b + (long)(kr + 1) * ldQ)
                                             : (Q1b + (long)(kr + 1 - K0) * ldQ)) + n0 + mq;
            e0 = *(const float4*)&s0[0]; e1 = *(const float4*)&s0[4];
            o0 = *(const float4*)&s1[0]; o1 = *(const float4*)&s1[4];
        }
    };
    auto storeT = [&](int buf) {
        float ev[8] = {e0.x,e0.y,e0.z,e0.w,e1.x,e1.y,e1.z,e1.w};
        float ov[8] = {o0.x,o0.y,o0.z,o0.w,o1.x,o1.y,o1.z,o1.w};
        uint32_t hs[8], ls[8];
#pragma unroll
        for (int m = 0; m < 8; m++) bsplit2(ev[m], ov[m], hs[m], ls[m]);
        uint32_t* H = side ? &QH[buf][k2][mq] : &PH[buf][k2][mq];
        uint32_t* L = side ? &QL[buf][k2][mq] : &PL[buf][k2][mq];
        *(uint4*)&H[0] = make_uint4(hs[0], hs[1], hs[2], hs[3]);
        *(uint4*)&H[4] = make_uint4(hs[4], hs[5], hs[6], hs[7]);
        *(uint4*)&L[0] = make_uint4(ls[0], ls[1], ls[2], ls[3]);
        *(uint4*)&L[4] = make_uint4(ls[4], ls[5], ls[6], ls[7]);
    };

    loadT(0); storeT(0);
    __syncthreads();

    for (int kt = 0; kt < ntiles; kt++) {
        const int cur = kt & 1, nxt = cur ^ 1;
        if (kt + 1 < ntiles) loadT((kt + 1) * 16);

        uint32_t bh[4][2], bl[4][2];
#pragma unroll
        for (int nt = 0; nt < 4; nt++) {
            int n = wn * 32 + nt * 8 + gid;
            bh[nt][0] = QH[cur][tig][n];     bh[nt][1] = QH[cur][tig + 4][n];
            bl[nt][0] = QL[cur][tig][n];     bl[nt][1] = QL[cur][tig + 4][n];
        }
#pragma unroll
        for (int mt = 0; mt < 4; mt++) {
            int m = wm * 64 + mt * 16 + gid;
            uint32_t ah[4] = {PH[cur][tig][m], PH[cur][tig][m + 8],
                              PH[cur][tig + 4][m], PH[cur][tig + 4][m + 8]};
            uint32_t al[4] = {PL[cur][tig][m], PL[cur][tig][m + 8],
                              PL[cur][tig + 4][m], PL[cur][tig + 4][m + 8]};
#pragma unroll
            for (int nt = 0; nt < 4; nt++) {
                mma16b(Cf[mt][nt], ah, bh[nt][0], bh[nt][1]);
                mma16b(Cf[mt][nt], ah, bl[nt][0], bl[nt][1]);
                mma16b(Cf[mt][nt], al, bh[nt][0], bh[nt][1]);
            }
        }
        if (kt + 1 < ntiles) { __syncthreads(); storeT(nxt); __syncthreads(); }
    }

    // epilogue
#pragma unroll
    for (int mt = 0; mt < 4; mt++) {
        int r0 = m0 + wm * 64 + mt * 16 + gid;
        float bi0 = 0.f, bi1 = 0.f;
        if (mode == 0) { bi0 = bias[r0]; bi1 = bias[r0 + 8]; }
#pragma unroll
        for (int nt = 0; nt < 4; nt++) {
            int cc = n0 + wn * 32 + nt * 8 + 2 * tig;
            float d0 = Cf[mt][nt][0], d1 = Cf[mt][nt][1];
            float d2 = Cf[mt][nt][2], d3 = Cf[mt][nt][3];
            if (mode == 0) {
                d0 = fmaxf(d0 + bi0, 0.f); d1 = fmaxf(d1 + bi0, 0.f);
                d2 = fmaxf(d2 + bi1, 0.f); d3 = fmaxf(d3 + bi1, 0.f);
            } else if (mode == 1) {
                d0 *= scale; d1 *= scale; d2 *= scale; d3 *= scale;
            }
            *(float2*)&Cb[(long)r0 * ldc + cc]       = make_float2(d0, d1);
            *(float2*)&Cb[(long)(r0 + 8) * ldc + cc] = make_float2(d2, d3);
        }
    }
}

// ---------------------------------------------------------------------------
// Halo attention (pixel-major) — unchanged from R11 (passing).
// ---------------------------------------------------------------------------
#define KW_OFF 0
#define KW_STR 68
#define QI_OFF 13600
#define QI_STR 68
#define ST_OFF 0
#define ST_STR 72
#define VJ_OFF 17952
#define VJ_STR 72
#define OT_OFF 0
#define OT_STR 68
#define RED_OFF 32352
#define MX_OFF 32864
#define INV_OFF 32928
#define SM_TOT 32992

__global__ __launch_bounds__(512, 1)
void attn_kernel(const float* __restrict__ gq, const float* __restrict__ gk,
                 const float* __restrict__ gv, const float* __restrict__ relh,
                 const float* __restrict__ relw, float* __restrict__ out)
{
    extern __shared__ float sm[];
    const int tid  = threadIdx.x;
    const int lane = tid & 31, w = tid >> 5;
    const int gid  = lane >> 2, tig = lane & 3;
    const int by = blockIdx.x >> 4, bx = blockIdx.x & 15;
    const int h = blockIdx.y, b = blockIdx.z;
    const int y0 = by * BLK, x0 = bx * BLK;
    const long qbase = (long)b * HW * 256 + h * 64;
    const long obase = ((long)b * CH + h * 64) * HW;

    if (tid < 272)      sm[KW_OFF + 196 * KW_STR + tid] = 0.f;
    else if (tid < 560) sm[VJ_OFF + 196 * VJ_STR + (tid - 272)] = 0.f;

    if (tid < 256) {
        int px = tid >> 2, quad = tid & 3;
        int p = (y0 + (px >> 3)) * IMG + x0 + (px & 7);
        const float* src = gq + qbase + (long)p * 256 + quad * 16;
        float* dst = &sm[QI_OFF + px * QI_STR + quad * 16];
#pragma unroll
        for (int f = 0; f < 4; f++) {
            float4 v = *(const float4*)(src + f * 4);
            *(float4*)&dst[f * 4] = make_float4(tf32r(v.x), tf32r(v.y),
                                                tf32r(v.z), tf32r(v.w));
        }
    }
    for (int u = tid; u < 1568; u += 512) {
        int isV = u >= 784;
        int e = isV ? u - 784 : u;
        int j = e >> 2, quad = e & 3;
        int iw = j / 14, jw = j - iw * 14;
        int yw = y0 - HALO + iw, xw = x0 - HALO + jw;
        bool valid = ((unsigned)yw < IMG) && ((unsigned)xw < IMG);
        int p = valid ? (yw * IMG + xw) : 0;
        if (!isV) {
            const float* src  = gk + qbase + (long)p * 256 + quad * 16;
            const float* bsrc = (quad < 2) ? (relh + iw * 32 + quad * 16)
                                           : (relw + jw * 32 + (quad - 2) * 16);
            float* dst = &sm[KW_OFF + j * KW_STR + quad * 16];
#pragma unroll
            for (int f = 0; f < 4; f++) {
                float4 bv = *(const float4*)(bsrc + f * 4);
                float4 kv = valid ? *(const float4*)(src + f * 4)
                                  : make_float4(0.f, 0.f, 0.f, 0.f);
                *(float4*)&dst[f * 4] =
                    make_float4(tf32r(kv.x + bv.x), tf32r(kv.y + bv.y),
                                tf32r(kv.z + bv.z), tf32r(kv.w + bv.w));
            }
        } else {
            const float* src = gv + qbase + (long)p * 256 + quad * 16;
            float* dst = &sm[VJ_OFF + j * VJ_STR + quad * 16];
#pragma unroll
            for (int f = 0; f < 4; f++) {
                float4 kv = valid ? *(const float4*)(src + f * 4)
                                  : make_float4(0.f, 0.f, 0.f, 0.f);
                *(float4*)&dst[f * 4] = make_float4(tf32r(kv.x), tf32r(kv.y),
                                                    tf32r(kv.z), tf32r(kv.w));
            }
        }
    }
    __syncthreads();

    const int wm = w >> 2, wn = w & 3;
    const int mcnt   = (wm == 0) ? 4 : 3;
    const int mtile0 = (wm == 0) ? 0 : (4 + 3 * (wm - 1));
    float Cf[4][2][4];
#pragma unroll
    for (int mt = 0; mt < 4; mt++)
#pragma unroll
        for (int nt = 0; nt < 2; nt++)
#pragma unroll
            for (int q = 0; q < 4; q++) Cf[mt][nt][q] = 0.f;

#pragma unroll
    for (int ks = 0; ks < 8; ks++) {
        const int c0 = ks * 8;
        uint32_t Bf[2][2];
#pragma unroll
        for (int nt = 0; nt < 2; nt++) {
            int n = wn * 16 + nt * 8 + gid;
            Bf[nt][0] = __float_as_uint(sm[QI_OFF + n * QI_STR + c0 + tig]);
            Bf[nt][1] = __float_as_uint(sm[QI_OFF + n * QI_STR + c0 + tig + 4]);
        }
#pragma unroll
        for (int mt = 0; mt < 4; mt++) {
            if (mt < mcnt) {
                int r = (mtile0 + mt) * 16 + gid;
                uint32_t a0 = __float_as_uint(sm[KW_OFF + r       * KW_STR + c0 + tig]);
                uint32_t a1 = __float_as_uint(sm[KW_OFF + (r + 8) * KW_STR + c0 + tig]);
                uint32_t a2 = __float_as_uint(sm[KW_OFF + r       * KW_STR + c0 + tig + 4]);
                uint32_t a3 = __float_as_uint(sm[KW_OFF + (r + 8) * KW_STR + c0 + tig + 4]);
                mma8(Cf[mt][0], a0, a1, a2, a3, Bf[0][0], Bf[0][1]);
                mma8(Cf[mt][1], a0, a1, a2, a3, Bf[1][0], Bf[1][1]);
            }
        }
    }
    __syncthreads();

#pragma unroll
    for (int mt = 0; mt < 4; mt++) {
        if (mt < mcnt) {
#pragma unroll
            for (int nt = 0; nt < 2; nt++) {
                int r = (mtile0 + mt) * 16 + gid;
                int ci = wn * 16 + nt * 8 + 2 * tig;
                *(float2*)&sm[ST_OFF + r * ST_STR + ci] =
                    make_float2(Cf[mt][nt][0], Cf[mt][nt][1]);
                if (r + 8 < 200)
                    *(float2*)&sm[ST_OFF + (r + 8) * ST_STR + ci] =
                        make_float2(Cf[mt][nt][2], Cf[mt][nt][3]);
            }
        }
    }
    __syncthreads();

    {
        const int i = tid & 63, p = tid >> 6;
        const int cnt = (p < 4) ? 25 : 24;
        const int jb  = (p < 4) ? p * 25 : 100 + (p - 4) * 24;
        float m = -1e30f;
        for (int jj = 0; jj < cnt; jj++)
            m = fmaxf(m, sm[ST_OFF + (jb + jj) * ST_STR + i]);
        sm[RED_OFF + p * 64 + i] = m;
        __syncthreads();
        if (tid < 64) {
            float mm = -1e30f;
#pragma unroll
            for (int pp = 0; pp < 8; pp++)
                mm = fmaxf(mm, sm[RED_OFF + pp * 64 + tid]);
            sm[MX_OFF + tid] = mm;
        }
        __syncthreads();
        float mm = sm[MX_OFF + i];
        float s = 0.f;
        for (int jj = 0; jj < cnt; jj++) {
            float e = __expf(sm[ST_OFF + (jb + jj) * ST_STR + i] - mm);
            s += e;
            sm[ST_OFF + (jb + jj) * ST_STR + i] = tf32r(e);
        }
        sm[RED_OFF + p * 64 + i] = s;
        if (tid < 4 * ST_STR) sm[ST_OFF + 196 * ST_STR + tid] = 0.f;
        __syncthreads();
        if (tid < 64) {
            float ss = 0.f;
#pragma unroll
            for (int pp = 0; pp < 8; pp++)
                ss += sm[RED_OFF + pp * 64 + tid];
            sm[INV_OFF + tid] = 1.f / ss;
        }
        __syncthreads();
    }

    {
        const int ibase = (w >> 2) * 16;
        const int wn2 = w & 3;
        float Df[2][4];
#pragma unroll
        for (int nt = 0; nt < 2; nt++)
#pragma unroll
            for (int q = 0; q < 4; q++) Df[nt][q] = 0.f;

        for (int kt = 0; kt < 25; kt++) {
            const int j0 = kt * 8;
            uint32_t a0 = __float_as_uint(sm[ST_OFF + (j0 + tig)     * ST_STR + ibase + gid]);
            uint32_t a1 = __float_as_uint(sm[ST_OFF + (j0 + tig)     * ST_STR + ibase + gid + 8]);
            uint32_t a2 = __float_as_uint(sm[ST_OFF + (j0 + tig + 4) * ST_STR + ibase + gid]);
            uint32_t a3 = __float_as_uint(sm[ST_OFF + (j0 + tig + 4) * ST_STR + ibase + gid + 8]);
#pragma unroll
            for (int nt = 0; nt < 2; nt++) {
                int c0 = wn2 * 16 + nt * 8;
                uint32_t b0 = __float_as_uint(sm[VJ_OFF + (j0 + tig)     * VJ_STR + c0 + gid]);
                uint32_t b1 = __float_as_uint(sm[VJ_OFF + (j0 + tig + 4) * VJ_STR + c0 + gid]);
                mma8(Df[nt], a0, a1, a2, a3, b0, b1);
            }
        }
        float v0 = sm[INV_OFF + ibase + gid];
        float v1 = sm[INV_OFF + ibase + gid + 8];
        __syncthreads();

#pragma unroll
        for (int nt = 0; nt < 2; nt++) {
            int c0 = wn2 * 16 + nt * 8;
            sm[OT_OFF + (c0 + 2*tig    ) * OT_STR + ibase + gid]     = Df[nt][0] * v0;
            sm[OT_OFF + (c0 + 2*tig + 1) * OT_STR + ibase + gid]     = Df[nt][1] * v0;
            sm[OT_OFF + (c0 + 2*tig    ) * OT_STR + ibase + gid + 8] = Df[nt][2] * v1;
            sm[OT_OFF + (c0 + 2*tig + 1) * OT_STR + ibase + gid + 8] = Df[nt][3] * v1;
        }
        __syncthreads();

        int c = tid >> 3, r = tid & 7;
        float4 o0 = *(const float4*)&sm[OT_OFF + c * OT_STR + r * 8];
        float4 o1 = *(const float4*)&sm[OT_OFF + c * OT_STR + r * 8 + 4];
        float* dst = out + obase + (long)c * HW + (y0 + r) * IMG + x0;
        *(float4*)&dst[0] = o0;
        *(float4*)&dst[4] = o1;
    }
}

// ---------------------------------------------------------------------------
extern "C" void kernel_launch(void* const* d_in, const int* in_sizes, int n_in,
                              void* d_out, int out_size)
{
    const float* noisy = (const float*)d_in[0];
    const float* aux   = (const float*)d_in[1];
    const float* w_map = (const float*)d_in[2];
    const float* b_map = (const float*)d_in[3];
    const float* w_q   = (const float*)d_in[4];
    const float* w_k   = (const float*)d_in[5];
    const float* w_v   = (const float*)d_in[6];
    const float* rel_h = (const float*)d_in[7];
    const float* rel_w = (const float*)d_in[8];
    float* out = (float*)d_out;

    float *naux, *q, *k, *v, *wt;
    cudaGetSymbolAddress((void**)&naux, g_naux);
    cudaGetSymbolAddress((void**)&q,    g_q);
    cudaGetSymbolAddress((void**)&k,    g_k);
    cudaGetSymbolAddress((void**)&v,    g_v);
    cudaGetSymbolAddress((void**)&wt,   g_wt);

    transpose_w<<<1280, 256>>>(w_map, w_q, w_k, w_v, wt);

    const long XB = (long)CH * HW;
    dim3 ggrid(128, 2, BATCH);
    // naux c-major: m=och (P = wmapT), n=pixels (Q = noisy|aux c-major)
    gemm_b<<<ggrid, 256>>>(wt, 0, 256, noisy, aux, XB, HW, 512, 256,
                           naux, HW, b_map, 1.f, 0, 0);
    // q/k/v pixel-major: m=pixels (P = X c-major), n=och (Q = wT)
    gemm_b<<<ggrid, 256>>>(naux,  XB, HW, wt + 131072, nullptr, 0, 256, 256, 256,
                           q, 256, nullptr, 0.125f, 1, 1);
    gemm_b<<<ggrid, 256>>>(naux,  XB, HW, wt + 196608, nullptr, 0, 256, 256, 256,
                           k, 256, nullptr, 1.f, 2, 1);
    gemm_b<<<ggrid, 256>>>(noisy, XB, HW, wt + 262144, nullptr, 0, 256, 256, 256,
                           v, 256, nullptr, 1.f, 2, 1);

    size_t smem = (size_t)SM_TOT * sizeof(float);
    cudaFuncSetAttribute(attn_kernel,
                         cudaFuncAttributeMaxDynamicSharedMemorySize, (int)smem);
    attn_kernel<<<dim3(NB * NB, HEADS, BATCH), 512, smem>>>(q, k, v, rel_h, rel_w, out);
}